// round 3
// baseline (speedup 1.0000x reference)
#include <cuda_runtime.h>
#include <math.h>

#define NN 50000
#define NE 800000

// ---------------- scratch (static __device__, 256B aligned, no allocation) ----------------
__device__ __align__(256) float g_deg[NN];
__device__ __align__(256) float g_dinv[NN];
__device__ __align__(256) int   g_counts[NN];
__device__ __align__(256) int   g_offsets[NN + 1];
__device__ __align__(256) int   g_cursor[NN];
__device__ __align__(256) int   g_csr_src[NE];
__device__ __align__(256) float g_csr_norm[NE];

__device__ __align__(256) float g_agg1[(size_t)NN * 256];  // agg(x)
__device__ __align__(256) float g_h1[(size_t)NN * 512];    // relu(agg1 @ W1 + b1)
__device__ __align__(256) float g_t2[(size_t)NN * 256];    // h1 @ W2
__device__ __align__(256) float g_h2[(size_t)NN * 256];    // relu(agg(t2) + b2)
__device__ __align__(256) float g_t3[(size_t)NN * 128];    // h2 @ W3

// ---------------- setup kernels ----------------
__global__ void k_init() {
    int i = blockIdx.x * blockDim.x + threadIdx.x;
    if (i < NN) { g_deg[i] = 1.0f; g_counts[i] = 0; }  // deg starts at self-loop weight 1
}

// edge_index is INT32 (JAX default config downcasts jnp.int64 -> int32)
__global__ void k_deg(const int* __restrict__ ei, const float* __restrict__ w) {
    int e = blockIdx.x * blockDim.x + threadIdx.x;
    if (e < NE) {
        int d = ei[NE + e];
        atomicAdd(&g_deg[d], w[e]);
        atomicAdd(&g_counts[d], 1);
    }
}

__global__ void k_dinv() {
    int i = blockIdx.x * blockDim.x + threadIdx.x;
    if (i < NN) {
        float dg = g_deg[i];
        g_dinv[i] = (dg > 0.0f) ? rsqrtf(dg) : 0.0f;
    }
}

// single-block exclusive scan of g_counts -> g_offsets (+ cursor copy)
__global__ void k_scan() {
    __shared__ int sh[1024];
    int t = threadIdx.x;
    const int per = (NN + 1023) / 1024;
    int start = t * per;
    int end = start + per; if (end > NN) end = NN; if (start > NN) start = NN;
    int s = 0;
    for (int i = start; i < end; i++) s += g_counts[i];
    sh[t] = s;
    __syncthreads();
    for (int off = 1; off < 1024; off <<= 1) {
        int v = (t >= off) ? sh[t - off] : 0;
        __syncthreads();
        sh[t] += v;
        __syncthreads();
    }
    int run = (t > 0) ? sh[t - 1] : 0;
    for (int i = start; i < end; i++) {
        g_offsets[i] = run;
        g_cursor[i] = run;
        run += g_counts[i];
    }
    if (t == 1023) g_offsets[NN] = sh[1023];
}

__global__ void k_scatter(const int* __restrict__ ei, const float* __restrict__ w) {
    int e = blockIdx.x * blockDim.x + threadIdx.x;
    if (e < NE) {
        int s = ei[e];
        int d = ei[NE + e];
        int pos = atomicAdd(&g_cursor[d], 1);
        g_csr_src[pos] = s;
        g_csr_norm[pos] = g_dinv[s] * w[e] * g_dinv[d];
    }
}

// ---------------- pull-style aggregation body: one warp per node ----------------
// out[n] = sum_{e: dst=n} in[src_e] * norm_e + dinv[n]^2 * in[n]  (+bias, relu)
template <int D, bool HASB, bool RELU>
__device__ __forceinline__ void agg_body(const float* __restrict__ in,
                                         const float* __restrict__ bias,
                                         float* __restrict__ out) {
    int node = (blockIdx.x * blockDim.x + threadIdx.x) >> 5;
    if (node >= NN) return;
    int lane = threadIdx.x & 31;

    constexpr int V = D / 128;  // float4s per lane
    float4 acc[V];

    float di = g_dinv[node];
    float sw = di * di;
    const float4* prow = (const float4*)(in + (size_t)node * D);
#pragma unroll
    for (int v = 0; v < V; v++) {
        float4 a = prow[v * 32 + lane];
        acc[v].x = a.x * sw; acc[v].y = a.y * sw; acc[v].z = a.z * sw; acc[v].w = a.w * sw;
    }

    int eb = g_offsets[node], ee = g_offsets[node + 1];
    for (int i = eb; i < ee; i++) {
        int s = g_csr_src[i];
        float nw = g_csr_norm[i];
        const float4* ps = (const float4*)(in + (size_t)s * D);
#pragma unroll
        for (int v = 0; v < V; v++) {
            float4 a = ps[v * 32 + lane];
            acc[v].x += a.x * nw; acc[v].y += a.y * nw;
            acc[v].z += a.z * nw; acc[v].w += a.w * nw;
        }
    }

    float4* pout = (float4*)(out + (size_t)node * D);
#pragma unroll
    for (int v = 0; v < V; v++) {
        float4 r = acc[v];
        if (HASB) {
            float4 bb = ((const float4*)bias)[v * 32 + lane];
            r.x += bb.x; r.y += bb.y; r.z += bb.z; r.w += bb.w;
        }
        if (RELU) {
            r.x = fmaxf(r.x, 0.0f); r.y = fmaxf(r.y, 0.0f);
            r.z = fmaxf(r.z, 0.0f); r.w = fmaxf(r.w, 0.0f);
        }
        pout[v * 32 + lane] = r;
    }
}

// ---------------- fp32 SGEMM body: 128x128 tile, BK=8, 8x8 per thread ----------------
template <bool HASB, bool RELU>
__device__ __forceinline__ void sgemm_body(const float* __restrict__ A,
                                           const float* __restrict__ B,
                                           const float* __restrict__ bias,
                                           float* __restrict__ C,
                                           int M, int N, int K) {
    __shared__ float As[8][128];
    __shared__ float Bs[8][128];

    int tid = threadIdx.x;
    int bx = blockIdx.x, by = blockIdx.y;
    int tx = tid & 15, ty = tid >> 4;

    float acc[8][8];
#pragma unroll
    for (int i = 0; i < 8; i++)
#pragma unroll
        for (int j = 0; j < 8; j++) acc[i][j] = 0.0f;

    int aRow = tid >> 1, aCol = (tid & 1) * 4;
    int bRow = tid >> 5, bCol = (tid & 31) * 4;
    int gRow = by * 128 + aRow;
    const float* Bp = B + bx * 128 + bCol;
    const float* Ap = A + (size_t)gRow * K + aCol;

    for (int k0 = 0; k0 < K; k0 += 8) {
        float4 a4 = make_float4(0.f, 0.f, 0.f, 0.f);
        if (gRow < M) a4 = *(const float4*)(Ap + k0);
        As[aCol + 0][aRow] = a4.x;
        As[aCol + 1][aRow] = a4.y;
        As[aCol + 2][aRow] = a4.z;
        As[aCol + 3][aRow] = a4.w;
        float4 b4 = *(const float4*)(Bp + (size_t)(k0 + bRow) * N);
        *(float4*)(&Bs[bRow][bCol]) = b4;
        __syncthreads();

#pragma unroll
        for (int k = 0; k < 8; k++) {
            float4 a0 = *(const float4*)&As[k][ty * 8];
            float4 a1 = *(const float4*)&As[k][ty * 8 + 4];
            float4 b0 = *(const float4*)&Bs[k][tx * 8];
            float4 b1 = *(const float4*)&Bs[k][tx * 8 + 4];
            float ar[8] = {a0.x, a0.y, a0.z, a0.w, a1.x, a1.y, a1.z, a1.w};
            float br[8] = {b0.x, b0.y, b0.z, b0.w, b1.x, b1.y, b1.z, b1.w};
#pragma unroll
            for (int i = 0; i < 8; i++)
#pragma unroll
                for (int j = 0; j < 8; j++) acc[i][j] = fmaf(ar[i], br[j], acc[i][j]);
        }
        __syncthreads();
    }

#pragma unroll
    for (int i = 0; i < 8; i++) {
        int row = by * 128 + ty * 8 + i;
        if (row >= M) continue;
        float* Cr = C + (size_t)row * N + bx * 128 + tx * 8;
#pragma unroll
        for (int j = 0; j < 8; j += 4) {
            float4 c = make_float4(acc[i][j], acc[i][j + 1], acc[i][j + 2], acc[i][j + 3]);
            if (HASB) {
                float4 bb = *(const float4*)(bias + bx * 128 + tx * 8 + j);
                c.x += bb.x; c.y += bb.y; c.z += bb.z; c.w += bb.w;
            }
            if (RELU) {
                c.x = fmaxf(c.x, 0.0f); c.y = fmaxf(c.y, 0.0f);
                c.z = fmaxf(c.z, 0.0f); c.w = fmaxf(c.w, 0.0f);
            }
            *(float4*)(Cr + j) = c;
        }
    }
}

// ---------------- stage wrappers: direct (compile-time) symbol references ----------------
__global__ void k_agg1(const float* __restrict__ x) {
    agg_body<256, false, false>(x, nullptr, g_agg1);
}
__global__ __launch_bounds__(256) void k_gemm1(const float* __restrict__ W1,
                                               const float* __restrict__ b1) {
    sgemm_body<true, true>(g_agg1, W1, b1, g_h1, NN, 512, 256);
}
__global__ __launch_bounds__(256) void k_gemm2(const float* __restrict__ W2) {
    sgemm_body<false, false>(g_h1, W2, nullptr, g_t2, NN, 256, 512);
}
__global__ void k_agg2(const float* __restrict__ b2) {
    agg_body<256, true, true>(g_t2, b2, g_h2);
}
__global__ __launch_bounds__(256) void k_gemm3(const float* __restrict__ W3) {
    sgemm_body<false, false>(g_h2, W3, nullptr, g_t3, NN, 128, 256);
}
__global__ void k_agg3(const float* __restrict__ b3, float* __restrict__ out) {
    agg_body<128, true, false>(g_t3, b3, out);
}

// ---------------- launch ----------------
extern "C" void kernel_launch(void* const* d_in, const int* in_sizes, int n_in,
                              void* d_out, int out_size) {
    const float* x  = (const float*)d_in[0];
    const int*   ei = (const int*)d_in[1];   // int32 edge_index, shape (2, NE)
    const float* w  = (const float*)d_in[2];
    const float* W1 = (const float*)d_in[3];
    const float* b1 = (const float*)d_in[4];
    const float* W2 = (const float*)d_in[5];
    const float* b2 = (const float*)d_in[6];
    const float* W3 = (const float*)d_in[7];
    const float* b3 = (const float*)d_in[8];
    float* out = (float*)d_out;

    // --- graph normalization + CSR build (per-launch, graph-capturable) ---
    k_init<<<(NN + 255) / 256, 256>>>();
    k_deg<<<(NE + 255) / 256, 256>>>(ei, w);
    k_dinv<<<(NN + 255) / 256, 256>>>();
    k_scan<<<1, 1024>>>();
    k_scatter<<<(NE + 255) / 256, 256>>>(ei, w);

    const int aggBlocks = (NN * 32 + 255) / 256;  // warp per node

    // layer 1: aggregate x (D=256), then GEMM 256->512 with bias+relu
    k_agg1<<<aggBlocks, 256>>>(x);
    {
        dim3 g(512 / 128, (NN + 127) / 128);
        k_gemm1<<<g, 256>>>(W1, b1);
    }

    // layer 2: GEMM 512->256 (no bias), then aggregate (D=256) + bias + relu
    {
        dim3 g(256 / 128, (NN + 127) / 128);
        k_gemm2<<<g, 256>>>(W2);
    }
    k_agg2<<<aggBlocks, 256>>>(b2);

    // layer 3: GEMM 256->128 (no bias), then aggregate (D=128) + bias (no relu)
    {
        dim3 g(128 / 128, (NN + 127) / 128);
        k_gemm3<<<g, 256>>>(W3);
    }
    k_agg3<<<aggBlocks, 256>>>(b3, out);
}

// round 11
// speedup vs baseline: 1.0735x; 1.0735x over previous
#include <cuda_runtime.h>
#include <math.h>

#define NN 50000
#define NE 800000
#define NBLK 196   // ceil(NN/256)

// ---------------- scratch (static __device__, 256B aligned, no allocation) ----------------
__device__ __align__(256) float g_deg[NN];
__device__ __align__(256) float g_dinv[NN];
__device__ __align__(256) int   g_counts[NN];
__device__ __align__(256) int   g_part[256];
__device__ __align__(256) int   g_offsets[NN + 1];
__device__ __align__(256) int   g_cursor[NN];
__device__ __align__(256) int   g_csr_src[NE];
__device__ __align__(256) float g_csr_norm[NE];

__device__ __align__(256) float g_agg1[(size_t)NN * 256];  // agg(x)
__device__ __align__(256) float g_h1[(size_t)NN * 512];    // relu(agg1 @ W1 + b1)
__device__ __align__(256) float g_t2[(size_t)NN * 256];    // h1 @ W2
__device__ __align__(256) float g_h2[(size_t)NN * 256];    // relu(agg(t2) + b2)
__device__ __align__(256) float g_t3[(size_t)NN * 128];    // h2 @ W3

// ---------------- setup kernels ----------------
__global__ void k_init() {
    int i = blockIdx.x * blockDim.x + threadIdx.x;
    if (i < NN) { g_deg[i] = 1.0f; g_counts[i] = 0; }  // deg starts at self-loop weight 1
}

// edge_index is INT32 (JAX default config downcasts jnp.int64 -> int32)
__global__ void k_deg(const int* __restrict__ ei, const float* __restrict__ w) {
    int e = blockIdx.x * blockDim.x + threadIdx.x;
    if (e < NE) {
        int d = ei[NE + e];
        atomicAdd(&g_deg[d], w[e]);
        atomicAdd(&g_counts[d], 1);
    }
}

__global__ void k_dinv() {
    int i = blockIdx.x * blockDim.x + threadIdx.x;
    if (i < NN) {
        float dg = g_deg[i];
        g_dinv[i] = (dg > 0.0f) ? rsqrtf(dg) : 0.0f;
    }
}

// hierarchical exclusive scan of g_counts -> g_offsets/g_cursor
__global__ void k_scan1() {
    __shared__ int sh[256];
    int t = threadIdx.x;
    int i = blockIdx.x * 256 + t;
    sh[t] = (i < NN) ? g_counts[i] : 0;
    __syncthreads();
    for (int off = 128; off > 0; off >>= 1) {
        if (t < off) sh[t] += sh[t + off];
        __syncthreads();
    }
    if (t == 0) g_part[blockIdx.x] = sh[0];
}
__global__ void k_scan2() {
    __shared__ int sh[256];
    int t = threadIdx.x;
    int v = (t < NBLK) ? g_part[t] : 0;
    sh[t] = v;
    __syncthreads();
    for (int off = 1; off < 256; off <<= 1) {
        int u = (t >= off) ? sh[t - off] : 0;
        __syncthreads();
        sh[t] += u;
        __syncthreads();
    }
    if (t < NBLK) g_part[t] = sh[t] - v;
}
__global__ void k_scan3() {
    __shared__ int sh[256];
    int t = threadIdx.x;
    int i = blockIdx.x * 256 + t;
    int v = (i < NN) ? g_counts[i] : 0;
    sh[t] = v;
    __syncthreads();
    for (int off = 1; off < 256; off <<= 1) {
        int u = (t >= off) ? sh[t - off] : 0;
        __syncthreads();
        sh[t] += u;
        __syncthreads();
    }
    int base = g_part[blockIdx.x];
    int excl = base + sh[t] - v;
    if (i < NN) { g_offsets[i] = excl; g_cursor[i] = excl; }
    if (i == NN - 1) g_offsets[NN] = excl + v;
}

__global__ void k_scatter(const int* __restrict__ ei, const float* __restrict__ w) {
    int e = blockIdx.x * blockDim.x + threadIdx.x;
    if (e < NE) {
        int s = ei[e];
        int d = ei[NE + e];
        int pos = atomicAdd(&g_cursor[d], 1);
        g_csr_src[pos] = s;
        g_csr_norm[pos] = g_dinv[s] * w[e] * g_dinv[d];
    }
}

// ---------------- pull-style aggregation body: one warp per node ----------------
// out[n] = sum_{e: dst=n} in[src_e] * norm_e + dinv[n]^2 * in[n]  (+bias, relu)
template <int D, bool HASB, bool RELU>
__device__ __forceinline__ void agg_body(const float* __restrict__ in,
                                         const float* __restrict__ bias,
                                         float* __restrict__ out) {
    int node = (blockIdx.x * blockDim.x + threadIdx.x) >> 5;
    if (node >= NN) return;
    int lane = threadIdx.x & 31;

    constexpr int V = D / 128;  // float4s per lane
    float4 acc[V];

    float di = g_dinv[node];
    float sw = di * di;
    const float4* prow = (const float4*)(in + (size_t)node * D);
#pragma unroll
    for (int v = 0; v < V; v++) {
        float4 a = prow[v * 32 + lane];
        acc[v].x = a.x * sw; acc[v].y = a.y * sw; acc[v].z = a.z * sw; acc[v].w = a.w * sw;
    }

    int eb = g_offsets[node], ee = g_offsets[node + 1];
    for (int i = eb; i < ee; i++) {
        int s = g_csr_src[i];
        float nw = g_csr_norm[i];
        const float4* ps = (const float4*)(in + (size_t)s * D);
#pragma unroll
        for (int v = 0; v < V; v++) {
            float4 a = ps[v * 32 + lane];
            acc[v].x += a.x * nw; acc[v].y += a.y * nw;
            acc[v].z += a.z * nw; acc[v].w += a.w * nw;
        }
    }

    float4* pout = (float4*)(out + (size_t)node * D);
#pragma unroll
    for (int v = 0; v < V; v++) {
        float4 r = acc[v];
        if (HASB) {
            float4 bb = ((const float4*)bias)[v * 32 + lane];
            r.x += bb.x; r.y += bb.y; r.z += bb.z; r.w += bb.w;
        }
        if (RELU) {
            r.x = fmaxf(r.x, 0.0f); r.y = fmaxf(r.y, 0.0f);
            r.z = fmaxf(r.z, 0.0f); r.w = fmaxf(r.w, 0.0f);
        }
        pout[v * 32 + lane] = r;
    }
}

// ---------------- fp32 SGEMM body: 128x128 tile, BK=8, 8x8 per thread ----------------
template <bool HASB, bool RELU>
__device__ __forceinline__ void sgemm_body(const float* __restrict__ A,
                                           const float* __restrict__ B,
                                           const float* __restrict__ bias,
                                           float* __restrict__ C,
                                           int M, int N, int K) {
    __shared__ float As[8][128];
    __shared__ float Bs[8][128];

    int tid = threadIdx.x;
    int bx = blockIdx.x, by = blockIdx.y;
    int tx = tid & 15, ty = tid >> 4;

    float acc[8][8];
#pragma unroll
    for (int i = 0; i < 8; i++)
#pragma unroll
        for (int j = 0; j < 8; j++) acc[i][j] = 0.0f;

    int aRow = tid >> 1, aCol = (tid & 1) * 4;
    int bRow = tid >> 5, bCol = (tid & 31) * 4;
    int gRow = by * 128 + aRow;
    const float* Bp = B + bx * 128 + bCol;
    const float* Ap = A + (size_t)gRow * K + aCol;

    for (int k0 = 0; k0 < K; k0 += 8) {
        float4 a4 = make_float4(0.f, 0.f, 0.f, 0.f);
        if (gRow < M) a4 = *(const float4*)(Ap + k0);
        As[aCol + 0][aRow] = a4.x;
        As[aCol + 1][aRow] = a4.y;
        As[aCol + 2][aRow] = a4.z;
        As[aCol + 3][aRow] = a4.w;
        float4 b4 = *(const float4*)(Bp + (size_t)(k0 + bRow) * N);
        *(float4*)(&Bs[bRow][bCol]) = b4;
        __syncthreads();

#pragma unroll
        for (int k = 0; k < 8; k++) {
            float4 a0 = *(const float4*)&As[k][ty * 8];
            float4 a1 = *(const float4*)&As[k][ty * 8 + 4];
            float4 b0 = *(const float4*)&Bs[k][tx * 8];
            float4 b1 = *(const float4*)&Bs[k][tx * 8 + 4];
            float ar[8] = {a0.x, a0.y, a0.z, a0.w, a1.x, a1.y, a1.z, a1.w};
            float br[8] = {b0.x, b0.y, b0.z, b0.w, b1.x, b1.y, b1.z, b1.w};
#pragma unroll
            for (int i = 0; i < 8; i++)
#pragma unroll
                for (int j = 0; j < 8; j++) acc[i][j] = fmaf(ar[i], br[j], acc[i][j]);
        }
        __syncthreads();
    }

#pragma unroll
    for (int i = 0; i < 8; i++) {
        int row = by * 128 + ty * 8 + i;
        if (row >= M) continue;
        float* Cr = C + (size_t)row * N + bx * 128 + tx * 8;
#pragma unroll
        for (int j = 0; j < 8; j += 4) {
            float4 c = make_float4(acc[i][j], acc[i][j + 1], acc[i][j + 2], acc[i][j + 3]);
            if (HASB) {
                float4 bb = *(const float4*)(bias + bx * 128 + tx * 8 + j);
                c.x += bb.x; c.y += bb.y; c.z += bb.z; c.w += bb.w;
            }
            if (RELU) {
                c.x = fmaxf(c.x, 0.0f); c.y = fmaxf(c.y, 0.0f);
                c.z = fmaxf(c.z, 0.0f); c.w = fmaxf(c.w, 0.0f);
            }
            *(float4*)(Cr + j) = c;
        }
    }
}

// ---------------- stage wrappers: direct (compile-time) symbol references ----------------
__global__ void k_agg1(const float* __restrict__ x) {
    agg_body<256, false, false>(x, nullptr, g_agg1);
}
__global__ __launch_bounds__(256) void k_gemm1(const float* __restrict__ W1,
                                               const float* __restrict__ b1) {
    sgemm_body<true, true>(g_agg1, W1, b1, g_h1, NN, 512, 256);
}
__global__ __launch_bounds__(256) void k_gemm2(const float* __restrict__ W2) {
    sgemm_body<false, false>(g_h1, W2, nullptr, g_t2, NN, 256, 512);
}
__global__ void k_agg2(const float* __restrict__ b2) {
    agg_body<256, true, true>(g_t2, b2, g_h2);
}
__global__ __launch_bounds__(256) void k_gemm3(const float* __restrict__ W3) {
    sgemm_body<false, false>(g_h2, W3, nullptr, g_t3, NN, 128, 256);
}
__global__ void k_agg3(const float* __restrict__ b3, float* __restrict__ out) {
    agg_body<128, true, false>(g_t3, b3, out);
}

// ---------------- launch ----------------
extern "C" void kernel_launch(void* const* d_in, const int* in_sizes, int n_in,
                              void* d_out, int out_size) {
    const float* x  = (const float*)d_in[0];
    const int*   ei = (const int*)d_in[1];   // int32 edge_index, shape (2, NE)
    const float* w  = (const float*)d_in[2];
    const float* W1 = (const float*)d_in[3];
    const float* b1 = (const float*)d_in[4];
    const float* W2 = (const float*)d_in[5];
    const float* b2 = (const float*)d_in[6];
    const float* W3 = (const float*)d_in[7];
    const float* b3 = (const float*)d_in[8];
    float* out = (float*)d_out;

    // --- graph normalization + CSR build (per-launch, graph-capturable) ---
    k_init<<<(NN + 255) / 256, 256>>>();
    k_deg<<<(NE + 255) / 256, 256>>>(ei, w);
    k_dinv<<<(NN + 255) / 256, 256>>>();
    k_scan1<<<NBLK, 256>>>();
    k_scan2<<<1, 256>>>();
    k_scan3<<<NBLK, 256>>>();
    k_scatter<<<(NE + 255) / 256, 256>>>(ei, w);

    const int aggBlocks = (NN * 32 + 255) / 256;  // warp per node

    // layer 1: aggregate x (D=256), then GEMM 256->512 with bias+relu
    k_agg1<<<aggBlocks, 256>>>(x);
    {
        dim3 g(512 / 128, (NN + 127) / 128);
        k_gemm1<<<g, 256>>>(W1, b1);
    }

    // layer 2: GEMM 512->256 (no bias), then aggregate (D=256) + bias + relu
    {
        dim3 g(256 / 128, (NN + 127) / 128);
        k_gemm2<<<g, 256>>>(W2);
    }
    k_agg2<<<aggBlocks, 256>>>(b2);

    // layer 3: GEMM 256->128 (no bias), then aggregate (D=128) + bias (no relu)
    {
        dim3 g(128 / 128, (NN + 127) / 128);
        k_gemm3<<<g, 256>>>(W3);
    }
    k_agg3<<<aggBlocks, 256>>>(b3, out);
}

// round 13
// speedup vs baseline: 1.3176x; 1.2274x over previous
#include <cuda_runtime.h>
#include <math.h>
#include <stdint.h>

#define NN 50000
#define NN_PAD 50048
#define NE 800000
#define NBLK 196   // ceil(NN/256)

// ---------------- scratch (static __device__; referenced ONLY from device code) ----------------
__device__ __align__(256) float g_deg[NN];
__device__ __align__(256) float g_dinv[NN];
__device__ __align__(256) int   g_counts[NN];
__device__ __align__(256) int   g_part[256];
__device__ __align__(256) int   g_offsets[NN + 1];
__device__ __align__(256) int   g_cursor[NN];
__device__ __align__(256) int   g_csr_src[NE];
__device__ __align__(256) float g_csr_norm[NE];

__device__ __align__(256) float g_agg1[(size_t)NN * 256];  // agg(x)
__device__ __align__(256) float g_h1[(size_t)NN * 512];    // relu(agg1 @ W1 + b1)
__device__ __align__(256) float g_t2[(size_t)NN * 256];    // h1 @ W2
__device__ __align__(256) float g_h2[(size_t)NN * 256];    // relu(agg(t2) + b2)
__device__ __align__(256) float g_t3[(size_t)NN * 128];    // h2 @ W3

// bf16 planes, 2 bf16 packed per uint32, K-major rows; pad rows harmless (outputs guarded)
__device__ __align__(256) uint32_t gA256h[(size_t)NN_PAD * 128];
__device__ __align__(256) uint32_t gA256l[(size_t)NN_PAD * 128];
__device__ __align__(256) uint32_t gA512h[(size_t)NN_PAD * 256];
__device__ __align__(256) uint32_t gA512l[(size_t)NN_PAD * 256];
__device__ __align__(256) uint32_t gB1h[512 * 128], gB1l[512 * 128];  // [n][kpair], K=256
__device__ __align__(256) uint32_t gB2h[256 * 256], gB2l[256 * 256];  // K=512
__device__ __align__(256) uint32_t gB3h[128 * 128], gB3l[128 * 128];  // K=256

// bf16 round-to-nearest-even, result in low 16 bits
__device__ __forceinline__ uint32_t f2bf(float f) {
    uint32_t u = __float_as_uint(f);
    return (u + 0x7FFFu + ((u >> 16) & 1u)) >> 16;
}

#define MMA(c0, c1, c2, c3, a0, a1, a2, a3, b0, b1) \
    asm volatile( \
        "mma.sync.aligned.m16n8k16.row.col.f32.bf16.bf16.f32 " \
        "{%0,%1,%2,%3},{%4,%5,%6,%7},{%8,%9},{%0,%1,%2,%3};" \
        : "+f"(c0), "+f"(c1), "+f"(c2), "+f"(c3) \
        : "r"(a0), "r"(a1), "r"(a2), "r"(a3), "r"(b0), "r"(b1))

// ---------------- setup kernels (R11-proven) ----------------
__global__ void k_init() {
    int i = blockIdx.x * blockDim.x + threadIdx.x;
    if (i < NN) { g_deg[i] = 1.0f; g_counts[i] = 0; }
}
__global__ void k_deg(const int* __restrict__ ei, const float* __restrict__ w) {
    int e = blockIdx.x * blockDim.x + threadIdx.x;
    if (e < NE) {
        int d = ei[NE + e];
        atomicAdd(&g_deg[d], w[e]);
        atomicAdd(&g_counts[d], 1);
    }
}
__global__ void k_dinv() {
    int i = blockIdx.x * blockDim.x + threadIdx.x;
    if (i < NN) {
        float dg = g_deg[i];
        g_dinv[i] = (dg > 0.0f) ? rsqrtf(dg) : 0.0f;
    }
}
__global__ void k_scan1() {
    __shared__ int sh[256];
    int t = threadIdx.x;
    int i = blockIdx.x * 256 + t;
    sh[t] = (i < NN) ? g_counts[i] : 0;
    __syncthreads();
    for (int off = 128; off > 0; off >>= 1) {
        if (t < off) sh[t] += sh[t + off];
        __syncthreads();
    }
    if (t == 0) g_part[blockIdx.x] = sh[0];
}
__global__ void k_scan2() {
    __shared__ int sh[256];
    int t = threadIdx.x;
    int v = (t < NBLK) ? g_part[t] : 0;
    sh[t] = v;
    __syncthreads();
    for (int off = 1; off < 256; off <<= 1) {
        int u = (t >= off) ? sh[t - off] : 0;
        __syncthreads();
        sh[t] += u;
        __syncthreads();
    }
    if (t < NBLK) g_part[t] = sh[t] - v;
}
__global__ void k_scan3() {
    __shared__ int sh[256];
    int t = threadIdx.x;
    int i = blockIdx.x * 256 + t;
    int v = (i < NN) ? g_counts[i] : 0;
    sh[t] = v;
    __syncthreads();
    for (int off = 1; off < 256; off <<= 1) {
        int u = (t >= off) ? sh[t - off] : 0;
        __syncthreads();
        sh[t] += u;
        __syncthreads();
    }
    int base = g_part[blockIdx.x];
    int excl = base + sh[t] - v;
    if (i < NN) { g_offsets[i] = excl; g_cursor[i] = excl; }
    if (i == NN - 1) g_offsets[NN] = excl + v;
}
__global__ void k_scatter(const int* __restrict__ ei, const float* __restrict__ w) {
    int e = blockIdx.x * blockDim.x + threadIdx.x;
    if (e < NE) {
        int s = ei[e];
        int d = ei[NE + e];
        int pos = atomicAdd(&g_cursor[d], 1);
        g_csr_src[pos] = s;
        g_csr_norm[pos] = g_dinv[s] * w[e] * g_dinv[d];
    }
}

// ---------------- pull aggregation (R11-proven) ----------------
template <int D, bool HASB, bool RELU>
__device__ __forceinline__ void agg_body(const float* __restrict__ in,
                                         const float* __restrict__ bias,
                                         float* __restrict__ out) {
    int node = (blockIdx.x * blockDim.x + threadIdx.x) >> 5;
    if (node >= NN) return;
    int lane = threadIdx.x & 31;
    constexpr int V = D / 128;
    float4 acc[V];
    float di = g_dinv[node];
    float sw = di * di;
    const float4* prow = (const float4*)(in + (size_t)node * D);
#pragma unroll
    for (int v = 0; v < V; v++) {
        float4 a = prow[v * 32 + lane];
        acc[v].x = a.x * sw; acc[v].y = a.y * sw; acc[v].z = a.z * sw; acc[v].w = a.w * sw;
    }
    int eb = g_offsets[node], ee = g_offsets[node + 1];
    for (int i = eb; i < ee; i++) {
        int s = g_csr_src[i];
        float nw = g_csr_norm[i];
        const float4* ps = (const float4*)(in + (size_t)s * D);
#pragma unroll
        for (int v = 0; v < V; v++) {
            float4 a = ps[v * 32 + lane];
            acc[v].x += a.x * nw; acc[v].y += a.y * nw;
            acc[v].z += a.z * nw; acc[v].w += a.w * nw;
        }
    }
    float4* pout = (float4*)(out + (size_t)node * D);
#pragma unroll
    for (int v = 0; v < V; v++) {
        float4 r = acc[v];
        if (HASB) {
            float4 bb = ((const float4*)bias)[v * 32 + lane];
            r.x += bb.x; r.y += bb.y; r.z += bb.z; r.w += bb.w;
        }
        if (RELU) {
            r.x = fmaxf(r.x, 0.0f); r.y = fmaxf(r.y, 0.0f);
            r.z = fmaxf(r.z, 0.0f); r.w = fmaxf(r.w, 0.0f);
        }
        pout[v * 32 + lane] = r;
    }
}
__global__ void k_agg1(const float* __restrict__ x) { agg_body<256, false, false>(x, nullptr, g_agg1); }
__global__ void k_agg2(const float* __restrict__ b2) { agg_body<256, true, true>(g_t2, b2, g_h2); }
__global__ void k_agg3(const float* __restrict__ b3, float* __restrict__ out) { agg_body<128, true, false>(g_t3, b3, out); }

// ---------------- bf16 split bodies + wrappers (symbols bound in device code) ----------------
__device__ __forceinline__ void split_body(const float* __restrict__ in,
                                           uint32_t* __restrict__ hi,
                                           uint32_t* __restrict__ lo, int npairs) {
    int i = blockIdx.x * blockDim.x + threadIdx.x;
    if (i < npairs) {
        float2 f = ((const float2*)in)[i];
        uint32_t h0 = f2bf(f.x), h1 = f2bf(f.y);
        float hf0 = __uint_as_float(h0 << 16);
        float hf1 = __uint_as_float(h1 << 16);
        uint32_t l0 = f2bf(f.x - hf0), l1 = f2bf(f.y - hf1);
        hi[i] = h0 | (h1 << 16);
        lo[i] = l0 | (l1 << 16);
    }
}
__global__ void ksp_agg1() { split_body(g_agg1, gA256h, gA256l, NN * 128); }
__global__ void ksp_h1()   { split_body(g_h1,   gA512h, gA512l, NN * 256); }
__global__ void ksp_h2()   { split_body(g_h2,   gA256h, gA256l, NN * 128); }

// W[k][n] (KxNt row-major, harness pointer) -> planes [n][kpair]
__device__ __forceinline__ void splitT_body(const float* __restrict__ W,
                                            uint32_t* __restrict__ hiT,
                                            uint32_t* __restrict__ loT, int K, int Nt) {
    int K2 = K >> 1;
    int i = blockIdx.x * blockDim.x + threadIdx.x;
    if (i < Nt * K2) {
        int n = i / K2, kp = i % K2;
        float f0 = W[(size_t)(2 * kp) * Nt + n];
        float f1 = W[(size_t)(2 * kp + 1) * Nt + n];
        uint32_t h0 = f2bf(f0), h1 = f2bf(f1);
        float hf0 = __uint_as_float(h0 << 16);
        float hf1 = __uint_as_float(h1 << 16);
        uint32_t l0 = f2bf(f0 - hf0), l1 = f2bf(f1 - hf1);
        hiT[i] = h0 | (h1 << 16);
        loT[i] = l0 | (l1 << 16);
    }
}
__global__ void kspT_w1(const float* __restrict__ W) { splitT_body(W, gB1h, gB1l, 256, 512); }
__global__ void kspT_w2(const float* __restrict__ W) { splitT_body(W, gB2h, gB2l, 512, 256); }
__global__ void kspT_w3(const float* __restrict__ W) { splitT_body(W, gB3h, gB3l, 256, 128); }

// ---------------- bf16 split GEMM body (R12 all-scalar) + wrappers ----------------
// C[M,Ntot] = split3(A[M,K]) @ split3(B[Ntot,K])^T over K'=3K.
// CTA 128x64, 8 warps of 32x32. BK=32 bf16 (16 u32/row). smem stride 20 u32.
template <bool HASB, bool RELU>
__device__ __forceinline__ void mm_body(
    const uint32_t* __restrict__ Ah, const uint32_t* __restrict__ Al,
    const uint32_t* __restrict__ Bh, const uint32_t* __restrict__ Bl,
    const float* __restrict__ bias, float* __restrict__ C, int Ntot, int K) {
    __shared__ uint32_t sA[128 * 20];  // 10240 B
    __shared__ uint32_t sB[64 * 20];   //  5120 B

    int K2 = K >> 1;
    int CPT = K >> 5;
    int NC = 3 * CPT;

    int tid = threadIdx.x, lane = tid & 31, wid = tid >> 5;
    int m0 = blockIdx.x * 128, n0 = blockIdx.y * 64;
    int wm = (wid >> 1) * 32, wn = (wid & 1) * 32;
    int g = lane >> 2, tg = lane & 3;

    float acc[2][4][4];
#pragma unroll
    for (int mt = 0; mt < 2; mt++)
#pragma unroll
        for (int nt = 0; nt < 4; nt++)
#pragma unroll
            for (int q = 0; q < 4; q++) acc[mt][nt][q] = 0.0f;

    int rowA = tid >> 1;
    int qA = (tid & 1) * 2;
    int rowB = tid >> 2;
    int qB = tid & 3;

    const uint32_t* ArowH = Ah + (size_t)(m0 + rowA) * K2;
    const uint32_t* ArowL = Al + (size_t)(m0 + rowA) * K2;
    const uint32_t* BrowH = Bh + (size_t)(n0 + rowB) * K2;
    const uint32_t* BrowL = Bl + (size_t)(n0 + rowB) * K2;

    uint4 pa0 = *(const uint4*)(ArowH + qA * 4);
    uint4 pa1 = *(const uint4*)(ArowH + (qA + 1) * 4);
    uint4 pb  = *(const uint4*)(BrowH + qB * 4);

    for (int c = 0; c < NC; c++) {
        __syncthreads();
        int sa = rowA * 20 + qA * 4;
        sA[sa + 0] = pa0.x; sA[sa + 1] = pa0.y; sA[sa + 2] = pa0.z; sA[sa + 3] = pa0.w;
        sA[sa + 4] = pa1.x; sA[sa + 5] = pa1.y; sA[sa + 6] = pa1.z; sA[sa + 7] = pa1.w;
        int sb = rowB * 20 + qB * 4;
        sB[sb + 0] = pb.x; sB[sb + 1] = pb.y; sB[sb + 2] = pb.z; sB[sb + 3] = pb.w;
        __syncthreads();

        if (c + 1 < NC) {
            int cc = c + 1;
            int t = cc / CPT;
            int kku = (cc % CPT) * 16;
            const uint32_t* Ap = (t == 2) ? ArowL : ArowH;
            const uint32_t* Bp = (t == 1) ? BrowL : BrowH;
            pa0 = *(const uint4*)(Ap + kku + qA * 4);
            pa1 = *(const uint4*)(Ap + kku + (qA + 1) * 4);
            pb  = *(const uint4*)(Bp + kku + qB * 4);
        }

#pragma unroll
        for (int kk8 = 0; kk8 < 16; kk8 += 8) {
            int ra = (wm + g) * 20 + kk8 + tg;
            uint32_t a00 = sA[ra];
            uint32_t a01 = sA[ra + 8 * 20];
            uint32_t a02 = sA[ra + 4];
            uint32_t a03 = sA[ra + 8 * 20 + 4];
            uint32_t a10 = sA[ra + 16 * 20];
            uint32_t a11 = sA[ra + 24 * 20];
            uint32_t a12 = sA[ra + 16 * 20 + 4];
            uint32_t a13 = sA[ra + 24 * 20 + 4];
#pragma unroll
            for (int nt = 0; nt < 4; nt++) {
                int rb = (wn + nt * 8 + g) * 20 + kk8 + tg;
                uint32_t b0 = sB[rb];
                uint32_t b1 = sB[rb + 4];
                MMA(acc[0][nt][0], acc[0][nt][1], acc[0][nt][2], acc[0][nt][3],
                    a00, a01, a02, a03, b0, b1);
                MMA(acc[1][nt][0], acc[1][nt][1], acc[1][nt][2], acc[1][nt][3],
                    a10, a11, a12, a13, b0, b1);
            }
        }
    }

#pragma unroll
    for (int mt = 0; mt < 2; mt++)
#pragma unroll
        for (int nt = 0; nt < 4; nt++) {
            int col = n0 + wn + nt * 8 + tg * 2;
            float v0 = acc[mt][nt][0], v1 = acc[mt][nt][1];
            float v2 = acc[mt][nt][2], v3 = acc[mt][nt][3];
            if (HASB) {
                float b0v = bias[col], b1v = bias[col + 1];
                v0 += b0v; v1 += b1v; v2 += b0v; v3 += b1v;
            }
            if (RELU) {
                v0 = fmaxf(v0, 0.0f); v1 = fmaxf(v1, 0.0f);
                v2 = fmaxf(v2, 0.0f); v3 = fmaxf(v3, 0.0f);
            }
            int r = m0 + wm + mt * 16 + g;
            if (r < NN) {
                C[(size_t)r * Ntot + col] = v0;
                C[(size_t)r * Ntot + col + 1] = v1;
            }
            if (r + 8 < NN) {
                C[(size_t)(r + 8) * Ntot + col] = v2;
                C[(size_t)(r + 8) * Ntot + col + 1] = v3;
            }
        }
}

__global__ void __launch_bounds__(256) kg1(const float* __restrict__ b1) {
    mm_body<true, true>(gA256h, gA256l, gB1h, gB1l, b1, g_h1, 512, 256);
}
__global__ void __launch_bounds__(256) kg2() {
    mm_body<false, false>(gA512h, gA512l, gB2h, gB2l, nullptr, g_t2, 256, 512);
}
__global__ void __launch_bounds__(256) kg3() {
    mm_body<false, false>(gA256h, gA256l, gB3h, gB3l, nullptr, g_t3, 128, 256);
}

// ---------------- launch (ONLY harness pointers cross the host/device boundary) ----------------
extern "C" void kernel_launch(void* const* d_in, const int* in_sizes, int n_in,
                              void* d_out, int out_size) {
    const float* x  = (const float*)d_in[0];
    const int*   ei = (const int*)d_in[1];   // int32 edge_index, shape (2, NE)
    const float* w  = (const float*)d_in[2];
    const float* W1 = (const float*)d_in[3];
    const float* b1 = (const float*)d_in[4];
    const float* W2 = (const float*)d_in[5];
    const float* b2 = (const float*)d_in[6];
    const float* W3 = (const float*)d_in[7];
    const float* b3 = (const float*)d_in[8];
    float* out = (float*)d_out;

    // --- graph normalization + CSR build ---
    k_init<<<(NN + 255) / 256, 256>>>();
    k_deg<<<(NE + 255) / 256, 256>>>(ei, w);
    k_dinv<<<(NN + 255) / 256, 256>>>();
    k_scan1<<<NBLK, 256>>>();
    k_scan2<<<1, 256>>>();
    k_scan3<<<NBLK, 256>>>();
    k_scatter<<<(NE + 255) / 256, 256>>>(ei, w);

    // weight splits
    kspT_w1<<<(512 * 128 + 255) / 256, 256>>>(W1);
    kspT_w2<<<(256 * 256 + 255) / 256, 256>>>(W2);
    kspT_w3<<<(128 * 128 + 255) / 256, 256>>>(W3);

    const int aggBlocks = (NN * 32 + 255) / 256;
    const int mTiles = NN_PAD / 128;  // 391

    // layer 1: agg(x) -> split -> mma GEMM(256->512)+bias+relu -> h1
    k_agg1<<<aggBlocks, 256>>>(x);
    ksp_agg1<<<(NN * 128 + 255) / 256, 256>>>();
    { dim3 gd(mTiles, 8); kg1<<<gd, 256>>>(b1); }

    // layer 2: split(h1) -> mma GEMM(512->256) -> t2 -> agg+bias+relu -> h2
    ksp_h1<<<(NN * 256 + 255) / 256, 256>>>();
    { dim3 gd(mTiles, 4); kg2<<<gd, 256>>>(); }
    k_agg2<<<aggBlocks, 256>>>(b2);

    // layer 3: split(h2) -> mma GEMM(256->128) -> t3 -> agg+bias -> out
    ksp_h2<<<(NN * 128 + 255) / 256, 256>>>();
    { dim3 gd(mTiles, 2); kg3<<<gd, 256>>>(); }
    k_agg3<<<aggBlocks, 256>>>(b3, out);
}

// round 14
// speedup vs baseline: 1.5032x; 1.1409x over previous
#include <cuda_runtime.h>
#include <math.h>
#include <stdint.h>

#define NN 50000
#define NN_PAD 50048
#define NE 800000
#define NBLK 196   // ceil(NN/256)

// ---------------- scratch (static __device__; referenced ONLY from device code) ----------------
__device__ __align__(256) float g_deg[NN];
__device__ __align__(256) float g_dinv[NN];
__device__ __align__(256) int   g_counts[NN];
__device__ __align__(256) int   g_part[256];
__device__ __align__(256) int   g_offsets[NN + 1];
__device__ __align__(256) int   g_cursor[NN];
__device__ __align__(256) int   g_csr_src[NE];
__device__ __align__(256) float g_csr_norm[NE];

__device__ __align__(256) float g_t2[(size_t)NN * 256];    // h1 @ W2 (fp32, agg2 input)
__device__ __align__(256) float g_t3[(size_t)NN * 128];    // h2 @ W3 (fp32, agg3 input)

// bf16 planes, 2 bf16 packed per uint32, K-major rows; pad rows stay zero (never written)
__device__ __align__(256) uint32_t gA256h[(size_t)NN_PAD * 128];
__device__ __align__(256) uint32_t gA256l[(size_t)NN_PAD * 128];
__device__ __align__(256) uint32_t gA512h[(size_t)NN_PAD * 256];
__device__ __align__(256) uint32_t gA512l[(size_t)NN_PAD * 256];
__device__ __align__(256) uint32_t gB1h[512 * 128], gB1l[512 * 128];  // [n][kpair], K=256
__device__ __align__(256) uint32_t gB2h[256 * 256], gB2l[256 * 256];  // K=512
__device__ __align__(256) uint32_t gB3h[128 * 128], gB3l[128 * 128];  // K=256

// bf16 round-to-nearest-even, result in low 16 bits
__device__ __forceinline__ uint32_t f2bf(float f) {
    uint32_t u = __float_as_uint(f);
    return (u + 0x7FFFu + ((u >> 16) & 1u)) >> 16;
}

#define MMA(c0, c1, c2, c3, a0, a1, a2, a3, b0, b1) \
    asm volatile( \
        "mma.sync.aligned.m16n8k16.row.col.f32.bf16.bf16.f32 " \
        "{%0,%1,%2,%3},{%4,%5,%6,%7},{%8,%9},{%0,%1,%2,%3};" \
        : "+f"(c0), "+f"(c1), "+f"(c2), "+f"(c3) \
        : "r"(a0), "r"(a1), "r"(a2), "r"(a3), "r"(b0), "r"(b1))

// ---------------- setup kernels (R11-proven) ----------------
__global__ void k_init() {
    int i = blockIdx.x * blockDim.x + threadIdx.x;
    if (i < NN) { g_deg[i] = 1.0f; g_counts[i] = 0; }
}
__global__ void k_deg(const int* __restrict__ ei, const float* __restrict__ w) {
    int e = blockIdx.x * blockDim.x + threadIdx.x;
    if (e < NE) {
        int d = ei[NE + e];
        atomicAdd(&g_deg[d], w[e]);
        atomicAdd(&g_counts[d], 1);
    }
}
__global__ void k_dinv() {
    int i = blockIdx.x * blockDim.x + threadIdx.x;
    if (i < NN) {
        float dg = g_deg[i];
        g_dinv[i] = (dg > 0.0f) ? rsqrtf(dg) : 0.0f;
    }
}
__global__ void k_scan1() {
    __shared__ int sh[256];
    int t = threadIdx.x;
    int i = blockIdx.x * 256 + t;
    sh[t] = (i < NN) ? g_counts[i] : 0;
    __syncthreads();
    for (int off = 128; off > 0; off >>= 1) {
        if (t < off) sh[t] += sh[t + off];
        __syncthreads();
    }
    if (t == 0) g_part[blockIdx.x] = sh[0];
}
__global__ void k_scan2() {
    __shared__ int sh[256];
    int t = threadIdx.x;
    int v = (t < NBLK) ? g_part[t] : 0;
    sh[t] = v;
    __syncthreads();
    for (int off = 1; off < 256; off <<= 1) {
        int u = (t >= off) ? sh[t - off] : 0;
        __syncthreads();
        sh[t] += u;
        __syncthreads();
    }
    if (t < NBLK) g_part[t] = sh[t] - v;
}
__global__ void k_scan3() {
    __shared__ int sh[256];
    int t = threadIdx.x;
    int i = blockIdx.x * 256 + t;
    int v = (i < NN) ? g_counts[i] : 0;
    sh[t] = v;
    __syncthreads();
    for (int off = 1; off < 256; off <<= 1) {
        int u = (t >= off) ? sh[t - off] : 0;
        __syncthreads();
        sh[t] += u;
        __syncthreads();
    }
    int base = g_part[blockIdx.x];
    int excl = base + sh[t] - v;
    if (i < NN) { g_offsets[i] = excl; g_cursor[i] = excl; }
    if (i == NN - 1) g_offsets[NN] = excl + v;
}
__global__ void k_scatter(const int* __restrict__ ei, const float* __restrict__ w) {
    int e = blockIdx.x * blockDim.x + threadIdx.x;
    if (e < NE) {
        int s = ei[e];
        int d = ei[NE + e];
        int pos = atomicAdd(&g_cursor[d], 1);
        g_csr_src[pos] = s;
        g_csr_norm[pos] = g_dinv[s] * w[e] * g_dinv[d];
    }
}

// ---------------- pull aggregation; SPLIT=true writes bf16 hi/lo planes ----------------
template <int D, bool HASB, bool RELU, bool SPLIT>
__device__ __forceinline__ void agg_body(const float* __restrict__ in,
                                         const float* __restrict__ bias,
                                         float* __restrict__ out,
                                         uint32_t* __restrict__ oh,
                                         uint32_t* __restrict__ ol) {
    int node = (blockIdx.x * blockDim.x + threadIdx.x) >> 5;
    if (node >= NN) return;
    int lane = threadIdx.x & 31;
    constexpr int V = D / 128;
    float4 acc[V];
    float di = g_dinv[node];
    float sw = di * di;
    const float4* prow = (const float4*)(in + (size_t)node * D);
#pragma unroll
    for (int v = 0; v < V; v++) {
        float4 a = prow[v * 32 + lane];
        acc[v].x = a.x * sw; acc[v].y = a.y * sw; acc[v].z = a.z * sw; acc[v].w = a.w * sw;
    }
    int eb = g_offsets[node], ee = g_offsets[node + 1];
    for (int i = eb; i < ee; i++) {
        int s = g_csr_src[i];
        float nw = g_csr_norm[i];
        const float4* ps = (const float4*)(in + (size_t)s * D);
#pragma unroll
        for (int v = 0; v < V; v++) {
            float4 a = ps[v * 32 + lane];
            acc[v].x += a.x * nw; acc[v].y += a.y * nw;
            acc[v].z += a.z * nw; acc[v].w += a.w * nw;
        }
    }
#pragma unroll
    for (int v = 0; v < V; v++) {
        float4 r = acc[v];
        if (HASB) {
            float4 bb = ((const float4*)bias)[v * 32 + lane];
            r.x += bb.x; r.y += bb.y; r.z += bb.z; r.w += bb.w;
        }
        if (RELU) {
            r.x = fmaxf(r.x, 0.0f); r.y = fmaxf(r.y, 0.0f);
            r.z = fmaxf(r.z, 0.0f); r.w = fmaxf(r.w, 0.0f);
        }
        if (!SPLIT) {
            ((float4*)(out + (size_t)node * D))[v * 32 + lane] = r;
        } else {
            uint32_t h0 = f2bf(r.x), h1 = f2bf(r.y), h2 = f2bf(r.z), h3 = f2bf(r.w);
            uint32_t l0 = f2bf(r.x - __uint_as_float(h0 << 16));
            uint32_t l1 = f2bf(r.y - __uint_as_float(h1 << 16));
            uint32_t l2 = f2bf(r.z - __uint_as_float(h2 << 16));
            uint32_t l3 = f2bf(r.w - __uint_as_float(h3 << 16));
            size_t base = (size_t)node * (D / 2) + v * 64 + lane * 2;
            oh[base] = h0 | (h1 << 16);
            oh[base + 1] = h2 | (h3 << 16);
            ol[base] = l0 | (l1 << 16);
            ol[base + 1] = l2 | (l3 << 16);
        }
    }
}
__global__ void k_agg1(const float* __restrict__ x) {
    agg_body<256, false, false, true>(x, nullptr, nullptr, gA256h, gA256l);
}
__global__ void k_agg2(const float* __restrict__ b2) {
    agg_body<256, true, true, true>(g_t2, b2, nullptr, gA256h, gA256l);
}
__global__ void k_agg3(const float* __restrict__ b3, float* __restrict__ out) {
    agg_body<128, true, false, false>(g_t3, b3, out, nullptr, nullptr);
}

// ---------------- weight split: W[k][n] (KxNt row-major) -> planes [n][kpair] ----------------
__device__ __forceinline__ void splitT_body(const float* __restrict__ W,
                                            uint32_t* __restrict__ hiT,
                                            uint32_t* __restrict__ loT, int K, int Nt) {
    int K2 = K >> 1;
    int i = blockIdx.x * blockDim.x + threadIdx.x;
    if (i < Nt * K2) {
        int n = i / K2, kp = i % K2;
        float f0 = W[(size_t)(2 * kp) * Nt + n];
        float f1 = W[(size_t)(2 * kp + 1) * Nt + n];
        uint32_t h0 = f2bf(f0), h1 = f2bf(f1);
        uint32_t l0 = f2bf(f0 - __uint_as_float(h0 << 16));
        uint32_t l1 = f2bf(f1 - __uint_as_float(h1 << 16));
        hiT[i] = h0 | (h1 << 16);
        loT[i] = l0 | (l1 << 16);
    }
}
__global__ void kspT_w1(const float* __restrict__ W) { splitT_body(W, gB1h, gB1l, 256, 512); }
__global__ void kspT_w2(const float* __restrict__ W) { splitT_body(W, gB2h, gB2l, 512, 256); }
__global__ void kspT_w3(const float* __restrict__ W) { splitT_body(W, gB3h, gB3l, 256, 128); }

// ---------------- bf16 split GEMM: double-buffered smem, one sync per chunk ----------------
// C[M,Ntot] = split3(A[M,K]) @ split3(B[Ntot,K])^T over K'=3K.
// CTA 128x64, 8 warps of 32x32. BK=32 bf16 (16 u32/row). smem stride 20 u32.
// OUTS=true: write bf16 hi/lo planes (OH/OL) instead of fp32 C.
template <bool HASB, bool RELU, bool OUTS>
__device__ __forceinline__ void mm_body(
    const uint32_t* __restrict__ Ah, const uint32_t* __restrict__ Al,
    const uint32_t* __restrict__ Bh, const uint32_t* __restrict__ Bl,
    const float* __restrict__ bias, float* __restrict__ C,
    uint32_t* __restrict__ OH, uint32_t* __restrict__ OL, int Ntot, int K) {
    __shared__ uint32_t sA[2 * 128 * 20];  // 20480 B
    __shared__ uint32_t sB[2 * 64 * 20];   // 10240 B

    int K2 = K >> 1;
    int CPT = K >> 5;
    int NC = 3 * CPT;

    int tid = threadIdx.x, lane = tid & 31, wid = tid >> 5;
    int m0 = blockIdx.x * 128, n0 = blockIdx.y * 64;
    int wm = (wid >> 1) * 32, wn = (wid & 1) * 32;
    int g = lane >> 2, tg = lane & 3;

    float acc[2][4][4];
#pragma unroll
    for (int mt = 0; mt < 2; mt++)
#pragma unroll
        for (int nt = 0; nt < 4; nt++)
#pragma unroll
            for (int q = 0; q < 4; q++) acc[mt][nt][q] = 0.0f;

    int rowA = tid >> 1;
    int qA = (tid & 1) * 2;
    int rowB = tid >> 2;
    int qB = tid & 3;

    const uint32_t* ArowH = Ah + (size_t)(m0 + rowA) * K2;
    const uint32_t* ArowL = Al + (size_t)(m0 + rowA) * K2;
    const uint32_t* BrowH = Bh + (size_t)(n0 + rowB) * K2;
    const uint32_t* BrowL = Bl + (size_t)(n0 + rowB) * K2;

    uint4 pa0 = *(const uint4*)(ArowH + qA * 4);
    uint4 pa1 = *(const uint4*)(ArowH + (qA + 1) * 4);
    uint4 pb  = *(const uint4*)(BrowH + qB * 4);

    for (int c = 0; c < NC; c++) {
        // store chunk c into buffer c&1 (WAR vs chunk c-2 readers covered by iter c-1 sync)
        int sbuf = (c & 1) * (128 * 20);
        int sbufB = (c & 1) * (64 * 20);
        int sa = sbuf + rowA * 20 + qA * 4;
        sA[sa + 0] = pa0.x; sA[sa + 1] = pa0.y; sA[sa + 2] = pa0.z; sA[sa + 3] = pa0.w;
        sA[sa + 4] = pa1.x; sA[sa + 5] = pa1.y; sA[sa + 6] = pa1.z; sA[sa + 7] = pa1.w;
        int sb = sbufB + rowB * 20 + qB * 4;
        sB[sb + 0] = pb.x; sB[sb + 1] = pb.y; sB[sb + 2] = pb.z; sB[sb + 3] = pb.w;

        if (c + 1 < NC) {   // issue global loads for chunk c+1 (land during compute)
            int cc = c + 1;
            int t = cc / CPT;
            int kku = (cc % CPT) * 16;
            const uint32_t* Ap = (t == 2) ? ArowL : ArowH;
            const uint32_t* Bp = (t == 1) ? BrowL : BrowH;
            pa0 = *(const uint4*)(Ap + kku + qA * 4);
            pa1 = *(const uint4*)(Ap + kku + (qA + 1) * 4);
            pb  = *(const uint4*)(Bp + kku + qB * 4);
        }

        __syncthreads();   // stores of chunk c visible; also fences chunk c-1 compute

#pragma unroll
        for (int kk8 = 0; kk8 < 16; kk8 += 8) {
            int ra = sbuf + (wm + g) * 20 + kk8 + tg;
            uint32_t a00 = sA[ra];
            uint32_t a01 = sA[ra + 8 * 20];
            uint32_t a02 = sA[ra + 4];
            uint32_t a03 = sA[ra + 8 * 20 + 4];
            uint32_t a10 = sA[ra + 16 * 20];
            uint32_t a11 = sA[ra + 24 * 20];
            uint32_t a12 = sA[ra + 16 * 20 + 4];
            uint32_t a13 = sA[ra + 24 * 20 + 4];
#pragma unroll
            for (int nt = 0; nt < 4; nt++) {
                int rb = sbufB + (wn + nt * 8 + g) * 20 + kk8 + tg;
                uint32_t b0 = sB[rb];
                uint32_t b1 = sB[rb + 4];
                MMA(acc[0][nt][0], acc[0][nt][1], acc[0][nt][2], acc[0][nt][3],
                    a00, a01, a02, a03, b0, b1);
                MMA(acc[1][nt][0], acc[1][nt][1], acc[1][nt][2], acc[1][nt][3],
                    a10, a11, a12, a13, b0, b1);
            }
        }
    }

    // epilogue
    int K2out = Ntot >> 1;
#pragma unroll
    for (int mt = 0; mt < 2; mt++)
#pragma unroll
        for (int nt = 0; nt < 4; nt++) {
            int col = n0 + wn + nt * 8 + tg * 2;
            float v0 = acc[mt][nt][0], v1 = acc[mt][nt][1];
            float v2 = acc[mt][nt][2], v3 = acc[mt][nt][3];
            if (HASB) {
                float b0v = bias[col], b1v = bias[col + 1];
                v0 += b0v; v1 += b1v; v2 += b0v; v3 += b1v;
            }
            if (RELU) {
                v0 = fmaxf(v0, 0.0f); v1 = fmaxf(v1, 0.0f);
                v2 = fmaxf(v2, 0.0f); v3 = fmaxf(v3, 0.0f);
            }
            int r = m0 + wm + mt * 16 + g;
            if (!OUTS) {
                if (r < NN) {
                    C[(size_t)r * Ntot + col] = v0;
                    C[(size_t)r * Ntot + col + 1] = v1;
                }
                if (r + 8 < NN) {
                    C[(size_t)(r + 8) * Ntot + col] = v2;
                    C[(size_t)(r + 8) * Ntot + col + 1] = v3;
                }
            } else {
                if (r < NN) {
                    uint32_t h0 = f2bf(v0), h1 = f2bf(v1);
                    uint32_t l0 = f2bf(v0 - __uint_as_float(h0 << 16));
                    uint32_t l1 = f2bf(v1 - __uint_as_float(h1 << 16));
                    size_t idx = (size_t)r * K2out + (col >> 1);
                    OH[idx] = h0 | (h1 << 16);
                    OL[idx] = l0 | (l1 << 16);
                }
                if (r + 8 < NN) {
                    uint32_t h2 = f2bf(v2), h3 = f2bf(v3);
                    uint32_t l2 = f2bf(v2 - __uint_as_float(h2 << 16));
                    uint32_t l3 = f2bf(v3 - __uint_as_float(h3 << 16));
                    size_t idx = (size_t)(r + 8) * K2out + (col >> 1);
                    OH[idx] = h2 | (h3 << 16);
                    OL[idx] = l2 | (l3 << 16);
                }
            }
        }
}

__global__ void __launch_bounds__(256) kg1(const float* __restrict__ b1) {
    mm_body<true, true, true>(gA256h, gA256l, gB1h, gB1l, b1,
                              nullptr, gA512h, gA512l, 512, 256);
}
__global__ void __launch_bounds__(256) kg2() {
    mm_body<false, false, false>(gA512h, gA512l, gB2h, gB2l, nullptr,
                                 g_t2, nullptr, nullptr, 256, 512);
}
__global__ void __launch_bounds__(256) kg3() {
    mm_body<false, false, false>(gA256h, gA256l, gB3h, gB3l, nullptr,
                                 g_t3, nullptr, nullptr, 128, 256);
}

// ---------------- launch (ONLY harness pointers cross the host/device boundary) ----------------
extern "C" void kernel_launch(void* const* d_in, const int* in_sizes, int n_in,
                              void* d_out, int out_size) {
    const float* x  = (const float*)d_in[0];
    const int*   ei = (const int*)d_in[1];   // int32 edge_index, shape (2, NE)
    const float* w  = (const float*)d_in[2];
    const float* W1 = (const float*)d_in[3];
    const float* b1 = (const float*)d_in[4];
    const float* W2 = (const float*)d_in[5];
    const float* b2 = (const float*)d_in[6];
    const float* W3 = (const float*)d_in[7];
    const float* b3 = (const float*)d_in[8];
    float* out = (float*)d_out;

    // --- graph normalization + CSR build ---
    k_init<<<(NN + 255) / 256, 256>>>();
    k_deg<<<(NE + 255) / 256, 256>>>(ei, w);
    k_dinv<<<(NN + 255) / 256, 256>>>();
    k_scan1<<<NBLK, 256>>>();
    k_scan2<<<1, 256>>>();
    k_scan3<<<NBLK, 256>>>();
    k_scatter<<<(NE + 255) / 256, 256>>>(ei, w);

    // weight splits
    kspT_w1<<<(512 * 128 + 255) / 256, 256>>>(W1);
    kspT_w2<<<(256 * 256 + 255) / 256, 256>>>(W2);
    kspT_w3<<<(128 * 128 + 255) / 256, 256>>>(W3);

    const int aggBlocks = (NN * 32 + 255) / 256;
    const int mTiles = NN_PAD / 128;  // 391

    // layer 1: agg(x) -> planes; GEMM(256->512)+bias+relu -> planes (h1)
    k_agg1<<<aggBlocks, 256>>>(x);
    { dim3 gd(mTiles, 8); kg1<<<gd, 256>>>(b1); }

    // layer 2: GEMM(512->256) -> t2 (fp32); agg+bias+relu -> planes (h2)
    { dim3 gd(mTiles, 4); kg2<<<gd, 256>>>(); }
    k_agg2<<<aggBlocks, 256>>>(b2);

    // layer 3: GEMM(256->128) -> t3 (fp32); agg+bias -> out
    { dim3 gd(mTiles, 2); kg3<<<gd, 256>>>(); }
    k_agg3<<<aggBlocks, 256>>>(b3, out);
}

// round 15
// speedup vs baseline: 1.6993x; 1.1305x over previous
#include <cuda_runtime.h>
#include <math.h>
#include <stdint.h>

#define NN 50000
#define NN_PAD 50048
#define NE 800000
#define NBLK 196   // ceil(NN/256)

// ---------------- scratch (static __device__; referenced ONLY from device code) ----------------
__device__ __align__(256) float g_deg[NN];
__device__ __align__(256) float g_dinv[NN];
__device__ __align__(256) int   g_counts[NN];
__device__ __align__(256) int   g_part[256];
__device__ __align__(256) int   g_offsets[NN + 1];
__device__ __align__(256) int   g_cursor[NN];
__device__ __align__(256) int   g_csr_src[NE];
__device__ __align__(256) float g_csr_norm[NE];

__device__ __align__(256) float g_t2[(size_t)NN * 256];    // h1 @ W2 (fp32, agg2 input)
__device__ __align__(256) float g_t3[(size_t)NN * 128];    // h2 @ W3 (fp32, agg3 input)

// bf16 planes, 2 bf16 packed per uint32, K-major rows; pad rows stay zero (never written)
__device__ __align__(256) uint32_t gA256h[(size_t)NN_PAD * 128];
__device__ __align__(256) uint32_t gA256l[(size_t)NN_PAD * 128];
__device__ __align__(256) uint32_t gA512h[(size_t)NN_PAD * 256];
__device__ __align__(256) uint32_t gA512l[(size_t)NN_PAD * 256];
__device__ __align__(256) uint32_t gB1h[512 * 128], gB1l[512 * 128];  // [n][kpair], K=256
__device__ __align__(256) uint32_t gB2h[256 * 256], gB2l[256 * 256];  // K=512
__device__ __align__(256) uint32_t gB3h[128 * 128], gB3l[128 * 128];  // K=256

// bf16 round-to-nearest-even, result in low 16 bits
__device__ __forceinline__ uint32_t f2bf(float f) {
    uint32_t u = __float_as_uint(f);
    return (u + 0x7FFFu + ((u >> 16) & 1u)) >> 16;
}

#define MMA(c0, c1, c2, c3, a0, a1, a2, a3, b0, b1) \
    asm volatile( \
        "mma.sync.aligned.m16n8k16.row.col.f32.bf16.bf16.f32 " \
        "{%0,%1,%2,%3},{%4,%5,%6,%7},{%8,%9},{%0,%1,%2,%3};" \
        : "+f"(c0), "+f"(c1), "+f"(c2), "+f"(c3) \
        : "r"(a0), "r"(a1), "r"(a2), "r"(a3), "r"(b0), "r"(b1))

// ---------------- setup kernels ----------------
__global__ void k_init() {
    int i = blockIdx.x * blockDim.x + threadIdx.x;
    if (i < NN) { g_deg[i] = 1.0f; g_counts[i] = 0; }
}
__global__ void k_deg(const int* __restrict__ ei, const float* __restrict__ w) {
    int e = blockIdx.x * blockDim.x + threadIdx.x;
    if (e < NE) {
        int d = ei[NE + e];
        atomicAdd(&g_deg[d], w[e]);
        atomicAdd(&g_counts[d], 1);
    }
}
__global__ void k_dinv() {
    int i = blockIdx.x * blockDim.x + threadIdx.x;
    if (i < NN) {
        float dg = g_deg[i];
        g_dinv[i] = (dg > 0.0f) ? rsqrtf(dg) : 0.0f;
    }
}
__global__ void k_scan1() {
    __shared__ int sh[256];
    int t = threadIdx.x;
    int i = blockIdx.x * 256 + t;
    sh[t] = (i < NN) ? g_counts[i] : 0;
    __syncthreads();
    for (int off = 128; off > 0; off >>= 1) {
        if (t < off) sh[t] += sh[t + off];
        __syncthreads();
    }
    if (t == 0) g_part[blockIdx.x] = sh[0];
}
__global__ void k_scan2() {
    __shared__ int sh[256];
    int t = threadIdx.x;
    int v = (t < NBLK) ? g_part[t] : 0;
    sh[t] = v;
    __syncthreads();
    for (int off = 1; off < 256; off <<= 1) {
        int u = (t >= off) ? sh[t - off] : 0;
        __syncthreads();
        sh[t] += u;
        __syncthreads();
    }
    if (t < NBLK) g_part[t] = sh[t] - v;
}
__global__ void k_scan3() {
    __shared__ int sh[256];
    int t = threadIdx.x;
    int i = blockIdx.x * 256 + t;
    int v = (i < NN) ? g_counts[i] : 0;
    sh[t] = v;
    __syncthreads();
    for (int off = 1; off < 256; off <<= 1) {
        int u = (t >= off) ? sh[t - off] : 0;
        __syncthreads();
        sh[t] += u;
        __syncthreads();
    }
    int base = g_part[blockIdx.x];
    int excl = base + sh[t] - v;
    if (i < NN) { g_offsets[i] = excl; g_cursor[i] = excl; }
    if (i == NN - 1) g_offsets[NN] = excl + v;
}
__global__ void k_scatter(const int* __restrict__ ei, const float* __restrict__ w) {
    int e = blockIdx.x * blockDim.x + threadIdx.x;
    if (e < NE) {
        int s = ei[e];
        int d = ei[NE + e];
        int pos = atomicAdd(&g_cursor[d], 1);
        g_csr_src[pos] = s;
        g_csr_norm[pos] = g_dinv[s] * w[e] * g_dinv[d];
    }
}

// ---------------- pull aggregation; SPLIT=true writes bf16 hi/lo planes ----------------
template <int D, bool HASB, bool RELU, bool SPLIT>
__device__ __forceinline__ void agg_body(const float* __restrict__ in,
                                         const float* __restrict__ bias,
                                         float* __restrict__ out,
                                         uint32_t* __restrict__ oh,
                                         uint32_t* __restrict__ ol) {
    int node = (blockIdx.x * blockDim.x + threadIdx.x) >> 5;
    if (node >= NN) return;
    int lane = threadIdx.x & 31;
    constexpr int V = D / 128;
    float4 acc[V];
    float di = g_dinv[node];
    float sw = di * di;
    const float4* prow = (const float4*)(in + (size_t)node * D);
#pragma unroll
    for (int v = 0; v < V; v++) {
        float4 a = prow[v * 32 + lane];
        acc[v].x = a.x * sw; acc[v].y = a.y * sw; acc[v].z = a.z * sw; acc[v].w = a.w * sw;
    }
    int eb = g_offsets[node], ee = g_offsets[node + 1];
    for (int i = eb; i < ee; i++) {
        int s = g_csr_src[i];
        float nw = g_csr_norm[i];
        const float4* ps = (const float4*)(in + (size_t)s * D);
#pragma unroll
        for (int v = 0; v < V; v++) {
            float4 a = ps[v * 32 + lane];
            acc[v].x += a.x * nw; acc[v].y += a.y * nw;
            acc[v].z += a.z * nw; acc[v].w += a.w * nw;
        }
    }
#pragma unroll
    for (int v = 0; v < V; v++) {
        float4 r = acc[v];
        if (HASB) {
            float4 bb = ((const float4*)bias)[v * 32 + lane];
            r.x += bb.x; r.y += bb.y; r.z += bb.z; r.w += bb.w;
        }
        if (RELU) {
            r.x = fmaxf(r.x, 0.0f); r.y = fmaxf(r.y, 0.0f);
            r.z = fmaxf(r.z, 0.0f); r.w = fmaxf(r.w, 0.0f);
        }
        if (!SPLIT) {
            ((float4*)(out + (size_t)node * D))[v * 32 + lane] = r;
        } else {
            uint32_t h0 = f2bf(r.x), h1 = f2bf(r.y), h2 = f2bf(r.z), h3 = f2bf(r.w);
            uint32_t l0 = f2bf(r.x - __uint_as_float(h0 << 16));
            uint32_t l1 = f2bf(r.y - __uint_as_float(h1 << 16));
            uint32_t l2 = f2bf(r.z - __uint_as_float(h2 << 16));
            uint32_t l3 = f2bf(r.w - __uint_as_float(h3 << 16));
            size_t base = (size_t)node * (D / 2) + v * 64 + lane * 2;
            oh[base] = h0 | (h1 << 16);
            oh[base + 1] = h2 | (h3 << 16);
            ol[base] = l0 | (l1 << 16);
            ol[base + 1] = l2 | (l3 << 16);
        }
    }
}
__global__ void k_agg1(const float* __restrict__ x) {
    agg_body<256, false, false, true>(x, nullptr, nullptr, gA256h, gA256l);
}
__global__ void k_agg2(const float* __restrict__ b2) {
    agg_body<256, true, true, true>(g_t2, b2, nullptr, gA256h, gA256l);
}
__global__ void k_agg3(const float* __restrict__ b3, float* __restrict__ out) {
    agg_body<128, true, false, false>(g_t3, b3, out, nullptr, nullptr);
}

// ---------------- weight split: W[k][n] (KxNt row-major) -> planes [n][kpair] ----------------
__device__ __forceinline__ void splitT_body(const float* __restrict__ W,
                                            uint32_t* __restrict__ hiT,
                                            uint32_t* __restrict__ loT, int K, int Nt) {
    int K2 = K >> 1;
    int i = blockIdx.x * blockDim.x + threadIdx.x;
    if (i < Nt * K2) {
        int n = i / K2, kp = i % K2;
        float f0 = W[(size_t)(2 * kp) * Nt + n];
        float f1 = W[(size_t)(2 * kp + 1) * Nt + n];
        uint32_t h0 = f2bf(f0), h1 = f2bf(f1);
        uint32_t l0 = f2bf(f0 - __uint_as_float(h0 << 16));
        uint32_t l1 = f2bf(f1 - __uint_as_float(h1 << 16));
        hiT[i] = h0 | (h1 << 16);
        loT[i] = l0 | (l1 << 16);
    }
}
__global__ void kspT_w1(const float* __restrict__ W) { splitT_body(W, gB1h, gB1l, 256, 512); }
__global__ void kspT_w2(const float* __restrict__ W) { splitT_body(W, gB2h, gB2l, 512, 256); }
__global__ void kspT_w3(const float* __restrict__ W) { splitT_body(W, gB3h, gB3l, 256, 128); }

// ---------------- bf16 split GEMM: CTA 128x128, warp 32x64, one sync per chunk ----------------
// C[M,Ntot] = split3(A[M,K]) @ split3(B[Ntot,K])^T over K'=3K.
// 8 warps in 4x2 grid of 32x64 tiles. BK=32 bf16 (16 u32/row). smem stride 20 u32.
// OUTS=true: write bf16 hi/lo planes (OH/OL) instead of fp32 C.
template <bool HASB, bool RELU, bool OUTS>
__device__ __forceinline__ void mm_body(
    const uint32_t* __restrict__ Ah, const uint32_t* __restrict__ Al,
    const uint32_t* __restrict__ Bh, const uint32_t* __restrict__ Bl,
    const float* __restrict__ bias, float* __restrict__ C,
    uint32_t* __restrict__ OH, uint32_t* __restrict__ OL, int Ntot, int K) {
    __shared__ uint32_t sA[2 * 128 * 20];  // 20480 B
    __shared__ uint32_t sB[2 * 128 * 20];  // 20480 B

    int K2 = K >> 1;
    int CPT = K >> 5;
    int NC = 3 * CPT;

    int tid = threadIdx.x, lane = tid & 31, wid = tid >> 5;
    int m0 = blockIdx.x * 128, n0 = blockIdx.y * 128;
    int wm = (wid >> 1) * 32, wn = (wid & 1) * 64;
    int g = lane >> 2, tg = lane & 3;

    float acc[2][8][4];
#pragma unroll
    for (int mt = 0; mt < 2; mt++)
#pragma unroll
        for (int nt = 0; nt < 8; nt++)
#pragma unroll
            for (int q = 0; q < 4; q++) acc[mt][nt][q] = 0.0f;

    int rowA = tid >> 1;            // 0..127
    int qA = (tid & 1) * 2;         // quad pair
    int rowB = tid >> 1;            // 0..127
    int qB = (tid & 1) * 2;

    const uint32_t* ArowH = Ah + (size_t)(m0 + rowA) * K2;
    const uint32_t* ArowL = Al + (size_t)(m0 + rowA) * K2;
    const uint32_t* BrowH = Bh + (size_t)(n0 + rowB) * K2;
    const uint32_t* BrowL = Bl + (size_t)(n0 + rowB) * K2;

    uint4 pa0 = *(const uint4*)(ArowH + qA * 4);
    uint4 pa1 = *(const uint4*)(ArowH + (qA + 1) * 4);
    uint4 pb0 = *(const uint4*)(BrowH + qB * 4);
    uint4 pb1 = *(const uint4*)(BrowH + (qB + 1) * 4);

    for (int c = 0; c < NC; c++) {
        // store chunk c into buffer c&1 (WAR vs chunk c-2 readers covered by iter c-1 sync)
        int sbuf = (c & 1) * (128 * 20);
        int sa = sbuf + rowA * 20 + qA * 4;
        sA[sa + 0] = pa0.x; sA[sa + 1] = pa0.y; sA[sa + 2] = pa0.z; sA[sa + 3] = pa0.w;
        sA[sa + 4] = pa1.x; sA[sa + 5] = pa1.y; sA[sa + 6] = pa1.z; sA[sa + 7] = pa1.w;
        int sb = sbuf + rowB * 20 + qB * 4;
        sB[sb + 0] = pb0.x; sB[sb + 1] = pb0.y; sB[sb + 2] = pb0.z; sB[sb + 3] = pb0.w;
        sB[sb + 4] = pb1.x; sB[sb + 5] = pb1.y; sB[sb + 6] = pb1.z; sB[sb + 7] = pb1.w;

        if (c + 1 < NC) {   // issue global loads for chunk c+1 (land during compute)
            int cc = c + 1;
            int t = cc / CPT;
            int kku = (cc % CPT) * 16;
            const uint32_t* Ap = (t == 2) ? ArowL : ArowH;
            const uint32_t* Bp = (t == 1) ? BrowL : BrowH;
            pa0 = *(const uint4*)(Ap + kku + qA * 4);
            pa1 = *(const uint4*)(Ap + kku + (qA + 1) * 4);
            pb0 = *(const uint4*)(Bp + kku + qB * 4);
            pb1 = *(const uint4*)(Bp + kku + (qB + 1) * 4);
        }

        __syncthreads();   // stores of chunk c visible; also fences chunk c-1 compute

#pragma unroll
        for (int kk8 = 0; kk8 < 16; kk8 += 8) {
            int ra = sbuf + (wm + g) * 20 + kk8 + tg;
            uint32_t a00 = sA[ra];
            uint32_t a01 = sA[ra + 8 * 20];
            uint32_t a02 = sA[ra + 4];
            uint32_t a03 = sA[ra + 8 * 20 + 4];
            uint32_t a10 = sA[ra + 16 * 20];
            uint32_t a11 = sA[ra + 24 * 20];
            uint32_t a12 = sA[ra + 16 * 20 + 4];
            uint32_t a13 = sA[ra + 24 * 20 + 4];
#pragma unroll
            for (int nt = 0; nt < 8; nt++) {
                int rb = sbuf + (wn + nt * 8 + g) * 20 + kk8 + tg;
                uint32_t b0 = sB[rb];
                uint32_t b1 = sB[rb + 4];
                MMA(acc[0][nt][0], acc[0][nt][1], acc[0][nt][2], acc[0][nt][3],
                    a00, a01, a02, a03, b0, b1);
                MMA(acc[1][nt][0], acc[1][nt][1], acc[1][nt][2], acc[1][nt][3],
                    a10, a11, a12, a13, b0, b1);
            }
        }
    }

    // epilogue
    int K2out = Ntot >> 1;
#pragma unroll
    for (int mt = 0; mt < 2; mt++)
#pragma unroll
        for (int nt = 0; nt < 8; nt++) {
            int col = n0 + wn + nt * 8 + tg * 2;
            float v0 = acc[mt][nt][0], v1 = acc[mt][nt][1];
            float v2 = acc[mt][nt][2], v3 = acc[mt][nt][3];
            if (HASB) {
                float b0v = bias[col], b1v = bias[col + 1];
                v0 += b0v; v1 += b1v; v2 += b0v; v3 += b1v;
            }
            if (RELU) {
                v0 = fmaxf(v0, 0.0f); v1 = fmaxf(v1, 0.0f);
                v2 = fmaxf(v2, 0.0f); v3 = fmaxf(v3, 0.0f);
            }
            int r = m0 + wm + mt * 16 + g;
            if (!OUTS) {
                if (r < NN) {
                    C[(size_t)r * Ntot + col] = v0;
                    C[(size_t)r * Ntot + col + 1] = v1;
                }
                if (r + 8 < NN) {
                    C[(size_t)(r + 8) * Ntot + col] = v2;
                    C[(size_t)(r + 8) * Ntot + col + 1] = v3;
                }
            } else {
                if (r < NN) {
                    uint32_t h0 = f2bf(v0), h1 = f2bf(v1);
                    uint32_t l0 = f2bf(v0 - __uint_as_float(h0 << 16));
                    uint32_t l1 = f2bf(v1 - __uint_as_float(h1 << 16));
                    size_t idx = (size_t)r * K2out + (col >> 1);
                    OH[idx] = h0 | (h1 << 16);
                    OL[idx] = l0 | (l1 << 16);
                }
                if (r + 8 < NN) {
                    uint32_t h2 = f2bf(v2), h3 = f2bf(v3);
                    uint32_t l2 = f2bf(v2 - __uint_as_float(h2 << 16));
                    uint32_t l3 = f2bf(v3 - __uint_as_float(h3 << 16));
                    size_t idx = (size_t)(r + 8) * K2out + (col >> 1);
                    OH[idx] = h2 | (h3 << 16);
                    OL[idx] = l2 | (l3 << 16);
                }
            }
        }
}

__global__ void __launch_bounds__(256) kg1(const float* __restrict__ b1) {
    mm_body<true, true, true>(gA256h, gA256l, gB1h, gB1l, b1,
                              nullptr, gA512h, gA512l, 512, 256);
}
__global__ void __launch_bounds__(256) kg2() {
    mm_body<false, false, false>(gA512h, gA512l, gB2h, gB2l, nullptr,
                                 g_t2, nullptr, nullptr, 256, 512);
}
__global__ void __launch_bounds__(256) kg3() {
    mm_body<false, false, false>(gA256h, gA256l, gB3h, gB3l, nullptr,
                                 g_t3, nullptr, nullptr, 128, 256);
}

// ---------------- launch (ONLY harness pointers cross the host/device boundary) ----------------
extern "C" void kernel_launch(void* const* d_in, const int* in_sizes, int n_in,
                              void* d_out, int out_size) {
    const float* x  = (const float*)d_in[0];
    const int*   ei = (const int*)d_in[1];   // int32 edge_index, shape (2, NE)
    const float* w  = (const float*)d_in[2];
    const float* W1 = (const float*)d_in[3];
    const float* b1 = (const float*)d_in[4];
    const float* W2 = (const float*)d_in[5];
    const float* b2 = (const float*)d_in[6];
    const float* W3 = (const float*)d_in[7];
    const float* b3 = (const float*)d_in[8];
    float* out = (float*)d_out;

    // --- graph normalization + CSR build ---
    k_init<<<(NN + 255) / 256, 256>>>();
    k_deg<<<(NE + 255) / 256, 256>>>(ei, w);
    k_dinv<<<(NN + 255) / 256, 256>>>();
    k_scan1<<<NBLK, 256>>>();
    k_scan2<<<1, 256>>>();
    k_scan3<<<NBLK, 256>>>();
    k_scatter<<<(NE + 255) / 256, 256>>>(ei, w);

    // weight splits
    kspT_w1<<<(512 * 128 + 255) / 256, 256>>>(W1);
    kspT_w2<<<(256 * 256 + 255) / 256, 256>>>(W2);
    kspT_w3<<<(128 * 128 + 255) / 256, 256>>>(W3);

    const int aggBlocks = (NN * 32 + 255) / 256;
    const int mTiles = NN_PAD / 128;  // 391

    // layer 1: agg(x) -> planes; GEMM(256->512)+bias+relu -> planes (h1)
    k_agg1<<<aggBlocks, 256>>>(x);
    { dim3 gd(mTiles, 4); kg1<<<gd, 256>>>(b1); }

    // layer 2: GEMM(512->256) -> t2 (fp32); agg+bias+relu -> planes (h2)
    { dim3 gd(mTiles, 2); kg2<<<gd, 256>>>(); }
    k_agg2<<<aggBlocks, 256>>>(b2);

    // layer 3: GEMM(256->128) -> t3 (fp32); agg+bias -> out
    { dim3 gd(mTiles, 1); kg3<<<gd, 256>>>(); }
    k_agg3<<<aggBlocks, 256>>>(b3, out);
}

// round 16
// speedup vs baseline: 1.7638x; 1.0379x over previous
#include <cuda_runtime.h>
#include <math.h>
#include <stdint.h>

#define NN 50000
#define NN_PAD 50048
#define NE 800000
#define NBLK 196   // ceil(NN/256)

// ---------------- scratch (static __device__; referenced ONLY from device code) ----------------
__device__ __align__(256) float g_deg[NN];
__device__ __align__(256) float g_dinv[NN];
__device__ __align__(256) int   g_counts[NN];
__device__ __align__(256) int   g_part[256];
__device__ __align__(256) int   g_offsets[NN + 1];
__device__ __align__(256) int   g_cursor[NN];
__device__ __align__(256) int   g_csr_src[NE];
__device__ __align__(256) float g_csr_norm[NE];

__device__ __align__(256) float g_t2[(size_t)NN * 256];    // h1 @ W2 (fp32, agg2 input)
__device__ __align__(256) float g_t3[(size_t)NN * 128];    // h2 @ W3 (fp32, agg3 input)

// bf16 planes, 2 bf16 packed per uint32, K-major rows; pad rows stay zero (never written)
__device__ __align__(256) uint32_t gA256h[(size_t)NN_PAD * 128];
__device__ __align__(256) uint32_t gA256l[(size_t)NN_PAD * 128];
__device__ __align__(256) uint32_t gA512h[(size_t)NN_PAD * 256];
__device__ __align__(256) uint32_t gA512l[(size_t)NN_PAD * 256];
__device__ __align__(256) uint32_t gB1h[512 * 128], gB1l[512 * 128];  // [n][kpair], K=256
__device__ __align__(256) uint32_t gB2h[256 * 256], gB2l[256 * 256];  // K=512
__device__ __align__(256) uint32_t gB3h[128 * 128], gB3l[128 * 128];  // K=256

// bf16 round-to-nearest-even, result in low 16 bits
__device__ __forceinline__ uint32_t f2bf(float f) {
    uint32_t u = __float_as_uint(f);
    return (u + 0x7FFFu + ((u >> 16) & 1u)) >> 16;
}

#define MMA(c0, c1, c2, c3, a0, a1, a2, a3, b0, b1) \
    asm volatile( \
        "mma.sync.aligned.m16n8k16.row.col.f32.bf16.bf16.f32 " \
        "{%0,%1,%2,%3},{%4,%5,%6,%7},{%8,%9},{%0,%1,%2,%3};" \
        : "+f"(c0), "+f"(c1), "+f"(c2), "+f"(c3) \
        : "r"(a0), "r"(a1), "r"(a2), "r"(a3), "r"(b0), "r"(b1))

// ---------------- setup kernels ----------------
__global__ void k_init() {
    int i = blockIdx.x * blockDim.x + threadIdx.x;
    if (i < NN) { g_deg[i] = 1.0f; g_counts[i] = 0; }
}
__global__ void k_deg(const int* __restrict__ ei, const float* __restrict__ w) {
    int e = blockIdx.x * blockDim.x + threadIdx.x;
    if (e < NE) {
        int d = ei[NE + e];
        atomicAdd(&g_deg[d], w[e]);
        atomicAdd(&g_counts[d], 1);
    }
}
// scan phase 1 + fused dinv (independent elementwise work on same index range)
__global__ void k_scan1() {
    __shared__ int sh[256];
    int t = threadIdx.x;
    int i = blockIdx.x * 256 + t;
    if (i < NN) {
        float dg = g_deg[i];
        g_dinv[i] = (dg > 0.0f) ? rsqrtf(dg) : 0.0f;
    }
    sh[t] = (i < NN) ? g_counts[i] : 0;
    __syncthreads();
    for (int off = 128; off > 0; off >>= 1) {
        if (t < off) sh[t] += sh[t + off];
        __syncthreads();
    }
    if (t == 0) g_part[blockIdx.x] = sh[0];
}
__global__ void k_scan2() {
    __shared__ int sh[256];
    int t = threadIdx.x;
    int v = (t < NBLK) ? g_part[t] : 0;
    sh[t] = v;
    __syncthreads();
    for (int off = 1; off < 256; off <<= 1) {
        int u = (t >= off) ? sh[t - off] : 0;
        __syncthreads();
        sh[t] += u;
        __syncthreads();
    }
    if (t < NBLK) g_part[t] = sh[t] - v;
}
__global__ void k_scan3() {
    __shared__ int sh[256];
    int t = threadIdx.x;
    int i = blockIdx.x * 256 + t;
    int v = (i < NN) ? g_counts[i] : 0;
    sh[t] = v;
    __syncthreads();
    for (int off = 1; off < 256; off <<= 1) {
        int u = (t >= off) ? sh[t - off] : 0;
        __syncthreads();
        sh[t] += u;
        __syncthreads();
    }
    int base = g_part[blockIdx.x];
    int excl = base + sh[t] - v;
    if (i < NN) { g_offsets[i] = excl; g_cursor[i] = excl; }
    if (i == NN - 1) g_offsets[NN] = excl + v;
}
__global__ void k_scatter(const int* __restrict__ ei, const float* __restrict__ w) {
    int e = blockIdx.x * blockDim.x + threadIdx.x;
    if (e < NE) {
        int s = ei[e];
        int d = ei[NE + e];
        int pos = atomicAdd(&g_cursor[d], 1);
        g_csr_src[pos] = s;
        g_csr_norm[pos] = g_dinv[s] * w[e] * g_dinv[d];
    }
}

// ---------------- pull aggregation; SPLIT=true writes bf16 hi/lo planes ----------------
template <int D, bool HASB, bool RELU, bool SPLIT>
__device__ __forceinline__ void agg_body(const float* __restrict__ in,
                                         const float* __restrict__ bias,
                                         float* __restrict__ out,
                                         uint32_t* __restrict__ oh,
                                         uint32_t* __restrict__ ol) {
    int node = (blockIdx.x * blockDim.x + threadIdx.x) >> 5;
    if (node >= NN) return;
    int lane = threadIdx.x & 31;
    constexpr int V = D / 128;
    float4 acc[V];
    float di = g_dinv[node];
    float sw = di * di;
    const float4* prow = (const float4*)(in + (size_t)node * D);
#pragma unroll
    for (int v = 0; v < V; v++) {
        float4 a = prow[v * 32 + lane];
        acc[v].x = a.x * sw; acc[v].y = a.y * sw; acc[v].z = a.z * sw; acc[v].w = a.w * sw;
    }
    int eb = g_offsets[node], ee = g_offsets[node + 1];
    for (int i = eb; i < ee; i++) {
        int s = g_csr_src[i];
        float nw = g_csr_norm[i];
        const float4* ps = (const float4*)(in + (size_t)s * D);
#pragma unroll
        for (int v = 0; v < V; v++) {
            float4 a = ps[v * 32 + lane];
            acc[v].x += a.x * nw; acc[v].y += a.y * nw;
            acc[v].z += a.z * nw; acc[v].w += a.w * nw;
        }
    }
#pragma unroll
    for (int v = 0; v < V; v++) {
        float4 r = acc[v];
        if (HASB) {
            float4 bb = ((const float4*)bias)[v * 32 + lane];
            r.x += bb.x; r.y += bb.y; r.z += bb.z; r.w += bb.w;
        }
        if (RELU) {
            r.x = fmaxf(r.x, 0.0f); r.y = fmaxf(r.y, 0.0f);
            r.z = fmaxf(r.z, 0.0f); r.w = fmaxf(r.w, 0.0f);
        }
        if (!SPLIT) {
            ((float4*)(out + (size_t)node * D))[v * 32 + lane] = r;
        } else {
            uint32_t h0 = f2bf(r.x), h1 = f2bf(r.y), h2 = f2bf(r.z), h3 = f2bf(r.w);
            uint32_t l0 = f2bf(r.x - __uint_as_float(h0 << 16));
            uint32_t l1 = f2bf(r.y - __uint_as_float(h1 << 16));
            uint32_t l2 = f2bf(r.z - __uint_as_float(h2 << 16));
            uint32_t l3 = f2bf(r.w - __uint_as_float(h3 << 16));
            size_t base = (size_t)node * (D / 2) + v * 64 + lane * 2;
            oh[base] = h0 | (h1 << 16);
            oh[base + 1] = h2 | (h3 << 16);
            ol[base] = l0 | (l1 << 16);
            ol[base + 1] = l2 | (l3 << 16);
        }
    }
}
__global__ void k_agg1(const float* __restrict__ x) {
    agg_body<256, false, false, true>(x, nullptr, nullptr, gA256h, gA256l);
}
__global__ void k_agg2(const float* __restrict__ b2) {
    agg_body<256, true, true, true>(g_t2, b2, nullptr, gA256h, gA256l);
}
__global__ void k_agg3(const float* __restrict__ b3, float* __restrict__ out) {
    agg_body<128, true, false, false>(g_t3, b3, out, nullptr, nullptr);
}

// ---------------- weight split: W[k][n] (KxNt row-major) -> planes [n][kpair] ----------------
__device__ __forceinline__ void splitT_body(const float* __restrict__ W,
                                            uint32_t* __restrict__ hiT,
                                            uint32_t* __restrict__ loT, int K, int Nt) {
    int K2 = K >> 1;
    int i = blockIdx.x * blockDim.x + threadIdx.x;
    if (i < Nt * K2) {
        int n = i / K2, kp = i % K2;
        float f0 = W[(size_t)(2 * kp) * Nt + n];
        float f1 = W[(size_t)(2 * kp + 1) * Nt + n];
        uint32_t h0 = f2bf(f0), h1 = f2bf(f1);
        uint32_t l0 = f2bf(f0 - __uint_as_float(h0 << 16));
        uint32_t l1 = f2bf(f1 - __uint_as_float(h1 << 16));
        hiT[i] = h0 | (h1 << 16);
        loT[i] = l0 | (l1 << 16);
    }
}
__global__ void kspT_w1(const float* __restrict__ W) { splitT_body(W, gB1h, gB1l, 256, 512); }
__global__ void kspT_w2(const float* __restrict__ W) { splitT_body(W, gB2h, gB2l, 512, 256); }
__global__ void kspT_w3(const float* __restrict__ W) { splitT_body(W, gB3h, gB3l, 256, 128); }

// ---------------- bf16 split GEMM: 4-plane single-stage, 3 terms per k-slice ----------------
// C[M,Ntot] = Ah@Bh^T + Ah@Bl^T + Al@Bh^T.  CTA 128x128, 8 warps of 32x64.
// Each k-slice (BK=32 bf16, 16 u32) loads all 4 planes ONCE; 3 mma terms run from smem.
// OUTS=true: write bf16 hi/lo planes (OH/OL) instead of fp32 C.
template <bool HASB, bool RELU, bool OUTS>
__device__ __forceinline__ void mm_body(
    const uint32_t* __restrict__ Ah, const uint32_t* __restrict__ Al,
    const uint32_t* __restrict__ Bh, const uint32_t* __restrict__ Bl,
    const float* __restrict__ bias, float* __restrict__ C,
    uint32_t* __restrict__ OH, uint32_t* __restrict__ OL, int Ntot, int K) {
    __shared__ uint32_t sAh[128 * 20];  // 10240 B each; 40 KB total
    __shared__ uint32_t sAl[128 * 20];
    __shared__ uint32_t sBh[128 * 20];
    __shared__ uint32_t sBl[128 * 20];

    int K2 = K >> 1;          // u32 per plane row
    int KC = K >> 5;          // k-slices of 32 bf16

    int tid = threadIdx.x, lane = tid & 31, wid = tid >> 5;
    int m0 = blockIdx.x * 128, n0 = blockIdx.y * 128;
    int wm = (wid >> 1) * 32, wn = (wid & 1) * 64;
    int g = lane >> 2, tg = lane & 3;

    float acc[2][8][4];
#pragma unroll
    for (int mt = 0; mt < 2; mt++)
#pragma unroll
        for (int nt = 0; nt < 8; nt++)
#pragma unroll
            for (int q = 0; q < 4; q++) acc[mt][nt][q] = 0.0f;

    int rowA = tid >> 1;            // 0..127
    int qA = (tid & 1) * 2;         // quad pair within 16-u32 slice

    const uint32_t* ArowH = Ah + (size_t)(m0 + rowA) * K2;
    const uint32_t* ArowL = Al + (size_t)(m0 + rowA) * K2;
    const uint32_t* BrowH = Bh + (size_t)(n0 + rowA) * K2;
    const uint32_t* BrowL = Bl + (size_t)(n0 + rowA) * K2;

    // prefetch slice 0 (all 4 planes)
    uint4 pah0 = *(const uint4*)(ArowH + qA * 4);
    uint4 pah1 = *(const uint4*)(ArowH + (qA + 1) * 4);
    uint4 pal0 = *(const uint4*)(ArowL + qA * 4);
    uint4 pal1 = *(const uint4*)(ArowL + (qA + 1) * 4);
    uint4 pbh0 = *(const uint4*)(BrowH + qA * 4);
    uint4 pbh1 = *(const uint4*)(BrowH + (qA + 1) * 4);
    uint4 pbl0 = *(const uint4*)(BrowL + qA * 4);
    uint4 pbl1 = *(const uint4*)(BrowL + (qA + 1) * 4);

    for (int kk = 0; kk < KC; kk++) {
        int sa = rowA * 20 + qA * 4;
        sAh[sa + 0] = pah0.x; sAh[sa + 1] = pah0.y; sAh[sa + 2] = pah0.z; sAh[sa + 3] = pah0.w;
        sAh[sa + 4] = pah1.x; sAh[sa + 5] = pah1.y; sAh[sa + 6] = pah1.z; sAh[sa + 7] = pah1.w;
        sAl[sa + 0] = pal0.x; sAl[sa + 1] = pal0.y; sAl[sa + 2] = pal0.z; sAl[sa + 3] = pal0.w;
        sAl[sa + 4] = pal1.x; sAl[sa + 5] = pal1.y; sAl[sa + 6] = pal1.z; sAl[sa + 7] = pal1.w;
        sBh[sa + 0] = pbh0.x; sBh[sa + 1] = pbh0.y; sBh[sa + 2] = pbh0.z; sBh[sa + 3] = pbh0.w;
        sBh[sa + 4] = pbh1.x; sBh[sa + 5] = pbh1.y; sBh[sa + 6] = pbh1.z; sBh[sa + 7] = pbh1.w;
        sBl[sa + 0] = pbl0.x; sBl[sa + 1] = pbl0.y; sBl[sa + 2] = pbl0.z; sBl[sa + 3] = pbl0.w;
        sBl[sa + 4] = pbl1.x; sBl[sa + 5] = pbl1.y; sBl[sa + 6] = pbl1.z; sBl[sa + 7] = pbl1.w;
        __syncthreads();

        if (kk + 1 < KC) {   // prefetch next slice into regs (lands during compute)
            int kku = (kk + 1) * 16;
            pah0 = *(const uint4*)(ArowH + kku + qA * 4);
            pah1 = *(const uint4*)(ArowH + kku + (qA + 1) * 4);
            pal0 = *(const uint4*)(ArowL + kku + qA * 4);
            pal1 = *(const uint4*)(ArowL + kku + (qA + 1) * 4);
            pbh0 = *(const uint4*)(BrowH + kku + qA * 4);
            pbh1 = *(const uint4*)(BrowH + kku + (qA + 1) * 4);
            pbl0 = *(const uint4*)(BrowL + kku + qA * 4);
            pbl1 = *(const uint4*)(BrowL + kku + (qA + 1) * 4);
        }

        // 3 terms from smem: Ah*Bh, Ah*Bl, Al*Bh
#pragma unroll
        for (int t = 0; t < 3; t++) {
            const uint32_t* As_ = (t == 2) ? sAl : sAh;
            const uint32_t* Bs_ = (t == 1) ? sBl : sBh;
#pragma unroll
            for (int kk8 = 0; kk8 < 16; kk8 += 8) {
                int ra = (wm + g) * 20 + kk8 + tg;
                uint32_t a00 = As_[ra];
                uint32_t a01 = As_[ra + 8 * 20];
                uint32_t a02 = As_[ra + 4];
                uint32_t a03 = As_[ra + 8 * 20 + 4];
                uint32_t a10 = As_[ra + 16 * 20];
                uint32_t a11 = As_[ra + 24 * 20];
                uint32_t a12 = As_[ra + 16 * 20 + 4];
                uint32_t a13 = As_[ra + 24 * 20 + 4];
#pragma unroll
                for (int nt = 0; nt < 8; nt++) {
                    int rb = (wn + nt * 8 + g) * 20 + kk8 + tg;
                    uint32_t b0 = Bs_[rb];
                    uint32_t b1 = Bs_[rb + 4];
                    MMA(acc[0][nt][0], acc[0][nt][1], acc[0][nt][2], acc[0][nt][3],
                        a00, a01, a02, a03, b0, b1);
                    MMA(acc[1][nt][0], acc[1][nt][1], acc[1][nt][2], acc[1][nt][3],
                        a10, a11, a12, a13, b0, b1);
                }
            }
        }
        __syncthreads();
    }

    // epilogue
    int K2out = Ntot >> 1;
#pragma unroll
    for (int mt = 0; mt < 2; mt++)
#pragma unroll
        for (int nt = 0; nt < 8; nt++) {
            int col = n0 + wn + nt * 8 + tg * 2;
            float v0 = acc[mt][nt][0], v1 = acc[mt][nt][1];
            float v2 = acc[mt][nt][2], v3 = acc[mt][nt][3];
            if (HASB) {
                float b0v = bias[col], b1v = bias[col + 1];
                v0 += b0v; v1 += b1v; v2 += b0v; v3 += b1v;
            }
            if (RELU) {
                v0 = fmaxf(v0, 0.0f); v1 = fmaxf(v1, 0.0f);
                v2 = fmaxf(v2, 0.0f); v3 = fmaxf(v3, 0.0f);
            }
            int r = m0 + wm + mt * 16 + g;
            if (!OUTS) {
                if (r < NN) {
                    C[(size_t)r * Ntot + col] = v0;
                    C[(size_t)r * Ntot + col + 1] = v1;
                }
                if (r + 8 < NN) {
                    C[(size_t)(r + 8) * Ntot + col] = v2;
                    C[(size_t)(r + 8) * Ntot + col + 1] = v3;
                }
            } else {
                if (r < NN) {
                    uint32_t h0 = f2bf(v0), h1 = f2bf(v1);
                    uint32_t l0 = f2bf(v0 - __uint_as_float(h0 << 16));
                    uint32_t l1 = f2bf(v1 - __uint_as_float(h1 << 16));
                    size_t idx = (size_t)r * K2out + (col >> 1);
                    OH[idx] = h0 | (h1 << 16);
                    OL[idx] = l0 | (l1 << 16);
                }
                if (r + 8 < NN) {
                    uint32_t h2 = f2bf(v2), h3 = f2bf(v3);
                    uint32_t l2 = f2bf(v2 - __uint_as_float(h2 << 16));
                    uint32_t l3 = f2bf(v3 - __uint_as_float(h3 << 16));
                    size_t idx = (size_t)(r + 8) * K2out + (col >> 1);
                    OH[idx] = h2 | (h3 << 16);
                    OL[idx] = l2 | (l3 << 16);
                }
            }
        }
}

__global__ void __launch_bounds__(256) kg1(const float* __restrict__ b1) {
    mm_body<true, true, true>(gA256h, gA256l, gB1h, gB1l, b1,
                              nullptr, gA512h, gA512l, 512, 256);
}
__global__ void __launch_bounds__(256) kg2() {
    mm_body<false, false, false>(gA512h, gA512l, gB2h, gB2l, nullptr,
                                 g_t2, nullptr, nullptr, 256, 512);
}
__global__ void __launch_bounds__(256) kg3() {
    mm_body<false, false, false>(gA256h, gA256l, gB3h, gB3l, nullptr,
                                 g_t3, nullptr, nullptr, 128, 256);
}

// ---------------- launch (ONLY harness pointers cross the host/device boundary) ----------------
extern "C" void kernel_launch(void* const* d_in, const int* in_sizes, int n_in,
                              void* d_out, int out_size) {
    const float* x  = (const float*)d_in[0];
    const int*   ei = (const int*)d_in[1];   // int32 edge_index, shape (2, NE)
    const float* w  = (const float*)d_in[2];
    const float* W1 = (const float*)d_in[3];
    const float* b1 = (const float*)d_in[4];
    const float* W2 = (const float*)d_in[5];
    const float* b2 = (const float*)d_in[6];
    const float* W3 = (const float*)d_in[7];
    const float* b3 = (const float*)d_in[8];
    float* out = (float*)d_out;

    // --- graph normalization + CSR build ---
    k_init<<<(NN + 255) / 256, 256>>>();
    k_deg<<<(NE + 255) / 256, 256>>>(ei, w);
    k_scan1<<<NBLK, 256>>>();     // + fused dinv
    k_scan2<<<1, 256>>>();
    k_scan3<<<NBLK, 256>>>();
    k_scatter<<<(NE + 255) / 256, 256>>>(ei, w);

    // weight splits
    kspT_w1<<<(512 * 128 + 255) / 256, 256>>>(W1);
    kspT_w2<<<(256 * 256 + 255) / 256, 256>>>(W2);
    kspT_w3<<<(128 * 128 + 255) / 256, 256>>>(W3);

    const int aggBlocks = (NN * 32 + 255) / 256;
    const int mTiles = NN_PAD / 128;  // 391

    // layer 1: agg(x) -> planes; GEMM(256->512)+bias+relu -> planes (h1)
    k_agg1<<<aggBlocks, 256>>>(x);
    { dim3 gd(mTiles, 4); kg1<<<gd, 256>>>(b1); }

    // layer 2: GEMM(512->256) -> t2 (fp32); agg+bias+relu -> planes (h2)
    { dim3 gd(mTiles, 2); kg2<<<gd, 256>>>(); }
    k_agg2<<<aggBlocks, 256>>>(b2);

    // layer 3: GEMM(256->128) -> t3 (fp32); agg+bias -> out
    { dim3 gd(mTiles, 1); kg3<<<gd, 256>>>(); }
    k_agg3<<<aggBlocks, 256>>>(b3, out);
}

// round 17
// speedup vs baseline: 1.8166x; 1.0299x over previous
#include <cuda_runtime.h>
#include <math.h>
#include <stdint.h>

#define NN 50000
#define NN_PAD 50048
#define NE 800000
#define NBLK 196   // ceil(NN/256)

// ---------------- scratch (static __device__; referenced ONLY from device code) ----------------
__device__ __align__(256) float g_deg[NN];
__device__ __align__(256) float g_dinv[NN];
__device__ __align__(256) int   g_counts[NN];
__device__ __align__(256) int   g_part[256];
__device__ __align__(256) int   g_offsets[NN + 1];
__device__ __align__(256) int   g_cursor[NN];
__device__ __align__(256) int2  g_csr[NE];          // (src, norm-as-int) packed

__device__ __align__(256) float g_t2[(size_t)NN * 256];    // h1 @ W2 (fp32, agg2 input)
__device__ __align__(256) float g_t3[(size_t)NN * 128];    // h2 @ W3 (fp32, agg3 input)

// bf16 planes, 2 bf16 packed per uint32, K-major rows; pad rows stay zero (never written)
__device__ __align__(256) uint32_t gA256h[(size_t)NN_PAD * 128];
__device__ __align__(256) uint32_t gA256l[(size_t)NN_PAD * 128];
__device__ __align__(256) uint32_t gA512h[(size_t)NN_PAD * 256];
__device__ __align__(256) uint32_t gA512l[(size_t)NN_PAD * 256];
__device__ __align__(256) uint32_t gB1h[512 * 128], gB1l[512 * 128];  // [n][kpair], K=256
__device__ __align__(256) uint32_t gB2h[256 * 256], gB2l[256 * 256];  // K=512
__device__ __align__(256) uint32_t gB3h[128 * 128], gB3l[128 * 128];  // K=256

// bf16 round-to-nearest-even, result in low 16 bits
__device__ __forceinline__ uint32_t f2bf(float f) {
    uint32_t u = __float_as_uint(f);
    return (u + 0x7FFFu + ((u >> 16) & 1u)) >> 16;
}

#define MMA(c0, c1, c2, c3, a0, a1, a2, a3, b0, b1) \
    asm volatile( \
        "mma.sync.aligned.m16n8k16.row.col.f32.bf16.bf16.f32 " \
        "{%0,%1,%2,%3},{%4,%5,%6,%7},{%8,%9},{%0,%1,%2,%3};" \
        : "+f"(c0), "+f"(c1), "+f"(c2), "+f"(c3) \
        : "r"(a0), "r"(a1), "r"(a2), "r"(a3), "r"(b0), "r"(b1))

// ---------------- fused setup: init + all three weight splits ----------------
// W[k][n] (KxNt row-major) -> planes [n][kpair]
__device__ __forceinline__ void splitT_idx(const float* __restrict__ W,
                                           uint32_t* __restrict__ hiT,
                                           uint32_t* __restrict__ loT,
                                           int K, int Nt, int i) {
    int K2 = K >> 1;
    if (i < Nt * K2) {
        int n = i / K2, kp = i % K2;
        float f0 = W[(size_t)(2 * kp) * Nt + n];
        float f1 = W[(size_t)(2 * kp + 1) * Nt + n];
        uint32_t h0 = f2bf(f0), h1 = f2bf(f1);
        uint32_t l0 = f2bf(f0 - __uint_as_float(h0 << 16));
        uint32_t l1 = f2bf(f1 - __uint_as_float(h1 << 16));
        hiT[i] = h0 | (h1 << 16);
        loT[i] = l0 | (l1 << 16);
    }
}
// blocks [0,196): init; [196,452): W1 split; [452,708): W2 split; [708,772): W3 split
__global__ void k_setup(const float* __restrict__ W1, const float* __restrict__ W2,
                        const float* __restrict__ W3) {
    int b = blockIdx.x;
    if (b < 196) {
        int i = b * 256 + threadIdx.x;
        if (i < NN) { g_deg[i] = 1.0f; g_counts[i] = 0; }
    } else if (b < 452) {
        splitT_idx(W1, gB1h, gB1l, 256, 512, (b - 196) * 256 + threadIdx.x);
    } else if (b < 708) {
        splitT_idx(W2, gB2h, gB2l, 512, 256, (b - 452) * 256 + threadIdx.x);
    } else {
        splitT_idx(W3, gB3h, gB3l, 256, 128, (b - 708) * 256 + threadIdx.x);
    }
}

__global__ void k_deg(const int* __restrict__ ei, const float* __restrict__ w) {
    int e = blockIdx.x * blockDim.x + threadIdx.x;
    if (e < NE) {
        int d = ei[NE + e];
        atomicAdd(&g_deg[d], w[e]);
        atomicAdd(&g_counts[d], 1);
    }
}
// scan phase 1 + fused dinv
__global__ void k_scan1() {
    __shared__ int sh[256];
    int t = threadIdx.x;
    int i = blockIdx.x * 256 + t;
    if (i < NN) {
        float dg = g_deg[i];
        g_dinv[i] = (dg > 0.0f) ? rsqrtf(dg) : 0.0f;
    }
    sh[t] = (i < NN) ? g_counts[i] : 0;
    __syncthreads();
    for (int off = 128; off > 0; off >>= 1) {
        if (t < off) sh[t] += sh[t + off];
        __syncthreads();
    }
    if (t == 0) g_part[blockIdx.x] = sh[0];
}
// scan phase 2+3 fused: per-block base via masked reduction of raw partials, then local scan
__global__ void k_scan3() {
    __shared__ int sh[256];
    int t = threadIdx.x;
    // base = sum of g_part[0..blockIdx.x)
    sh[t] = (t < blockIdx.x && t < NBLK) ? g_part[t] : 0;
    __syncthreads();
    for (int off = 128; off > 0; off >>= 1) {
        if (t < off) sh[t] += sh[t + off];
        __syncthreads();
    }
    int base = sh[0];
    __syncthreads();
    // local inclusive scan of counts
    int i = blockIdx.x * 256 + t;
    int v = (i < NN) ? g_counts[i] : 0;
    sh[t] = v;
    __syncthreads();
    for (int off = 1; off < 256; off <<= 1) {
        int u = (t >= off) ? sh[t - off] : 0;
        __syncthreads();
        sh[t] += u;
        __syncthreads();
    }
    int excl = base + sh[t] - v;
    if (i < NN) { g_offsets[i] = excl; g_cursor[i] = excl; }
    if (i == NN - 1) g_offsets[NN] = excl + v;
}
__global__ void k_scatter(const int* __restrict__ ei, const float* __restrict__ w) {
    int e = blockIdx.x * blockDim.x + threadIdx.x;
    if (e < NE) {
        int s = ei[e];
        int d = ei[NE + e];
        int pos = atomicAdd(&g_cursor[d], 1);
        float nm = g_dinv[s] * w[e] * g_dinv[d];
        g_csr[pos] = make_int2(s, __float_as_int(nm));
    }
}

// ---------------- pull aggregation; SPLIT=true writes bf16 hi/lo planes ----------------
template <int D, bool HASB, bool RELU, bool SPLIT>
__device__ __forceinline__ void agg_body(const float* __restrict__ in,
                                         const float* __restrict__ bias,
                                         float* __restrict__ out,
                                         uint32_t* __restrict__ oh,
                                         uint32_t* __restrict__ ol) {
    int node = (blockIdx.x * blockDim.x + threadIdx.x) >> 5;
    if (node >= NN) return;
    int lane = threadIdx.x & 31;
    constexpr int V = D / 128;
    float4 acc[V];
    float di = g_dinv[node];
    float sw = di * di;
    const float4* prow = (const float4*)(in + (size_t)node * D);
#pragma unroll
    for (int v = 0; v < V; v++) {
        float4 a = prow[v * 32 + lane];
        acc[v].x = a.x * sw; acc[v].y = a.y * sw; acc[v].z = a.z * sw; acc[v].w = a.w * sw;
    }
    int eb = g_offsets[node], ee = g_offsets[node + 1];
    int i = eb;
    for (; i + 2 <= ee; i += 2) {   // unroll-2: both rows' loads in flight together
        int2 e0 = g_csr[i];
        int2 e1 = g_csr[i + 1];
        float nw0 = __int_as_float(e0.y);
        float nw1 = __int_as_float(e1.y);
        const float4* p0 = (const float4*)(in + (size_t)e0.x * D);
        const float4* p1 = (const float4*)(in + (size_t)e1.x * D);
#pragma unroll
        for (int v = 0; v < V; v++) {
            float4 a0 = p0[v * 32 + lane];
            float4 a1 = p1[v * 32 + lane];
            acc[v].x += a0.x * nw0; acc[v].y += a0.y * nw0;
            acc[v].z += a0.z * nw0; acc[v].w += a0.w * nw0;
            acc[v].x += a1.x * nw1; acc[v].y += a1.y * nw1;
            acc[v].z += a1.z * nw1; acc[v].w += a1.w * nw1;
        }
    }
    if (i < ee) {
        int2 e0 = g_csr[i];
        float nw0 = __int_as_float(e0.y);
        const float4* p0 = (const float4*)(in + (size_t)e0.x * D);
#pragma unroll
        for (int v = 0; v < V; v++) {
            float4 a0 = p0[v * 32 + lane];
            acc[v].x += a0.x * nw0; acc[v].y += a0.y * nw0;
            acc[v].z += a0.z * nw0; acc[v].w += a0.w * nw0;
        }
    }
#pragma unroll
    for (int v = 0; v < V; v++) {
        float4 r = acc[v];
        if (HASB) {
            float4 bb = ((const float4*)bias)[v * 32 + lane];
            r.x += bb.x; r.y += bb.y; r.z += bb.z; r.w += bb.w;
        }
        if (RELU) {
            r.x = fmaxf(r.x, 0.0f); r.y = fmaxf(r.y, 0.0f);
            r.z = fmaxf(r.z, 0.0f); r.w = fmaxf(r.w, 0.0f);
        }
        if (!SPLIT) {
            ((float4*)(out + (size_t)node * D))[v * 32 + lane] = r;
        } else {
            uint32_t h0 = f2bf(r.x), h1 = f2bf(r.y), h2 = f2bf(r.z), h3 = f2bf(r.w);
            uint32_t l0 = f2bf(r.x - __uint_as_float(h0 << 16));
            uint32_t l1 = f2bf(r.y - __uint_as_float(h1 << 16));
            uint32_t l2 = f2bf(r.z - __uint_as_float(h2 << 16));
            uint32_t l3 = f2bf(r.w - __uint_as_float(h3 << 16));
            size_t base = (size_t)node * (D / 2) + v * 64 + lane * 2;
            oh[base] = h0 | (h1 << 16);
            oh[base + 1] = h2 | (h3 << 16);
            ol[base] = l0 | (l1 << 16);
            ol[base + 1] = l2 | (l3 << 16);
        }
    }
}
__global__ void k_agg1(const float* __restrict__ x) {
    agg_body<256, false, false, true>(x, nullptr, nullptr, gA256h, gA256l);
}
__global__ void k_agg2(const float* __restrict__ b2) {
    agg_body<256, true, true, true>(g_t2, b2, nullptr, gA256h, gA256l);
}
__global__ void k_agg3(const float* __restrict__ b3, float* __restrict__ out) {
    agg_body<128, true, false, false>(g_t3, b3, out, nullptr, nullptr);
}

// ---------------- bf16 split GEMM: 4-plane single-stage, 3 terms per k-slice ----------------
// C[M,Ntot] = Ah@Bh^T + Ah@Bl^T + Al@Bh^T.  CTA 128x128, 8 warps of 32x64.
// OUTS=true: write bf16 hi/lo planes (OH/OL) instead of fp32 C.
template <bool HASB, bool RELU, bool OUTS>
__device__ __forceinline__ void mm_body(
    const uint32_t* __restrict__ Ah, const uint32_t* __restrict__ Al,
    const uint32_t* __restrict__ Bh, const uint32_t* __restrict__ Bl,
    const float* __restrict__ bias, float* __restrict__ C,
    uint32_t* __restrict__ OH, uint32_t* __restrict__ OL, int Ntot, int K) {
    __shared__ uint32_t sAh[128 * 20];  // 10240 B each; 40 KB total
    __shared__ uint32_t sAl[128 * 20];
    __shared__ uint32_t sBh[128 * 20];
    __shared__ uint32_t sBl[128 * 20];

    int K2 = K >> 1;          // u32 per plane row
    int KC = K >> 5;          // k-slices of 32 bf16

    int tid = threadIdx.x, lane = tid & 31, wid = tid >> 5;
    int m0 = blockIdx.x * 128, n0 = blockIdx.y * 128;
    int wm = (wid >> 1) * 32, wn = (wid & 1) * 64;
    int g = lane >> 2, tg = lane & 3;

    float acc[2][8][4];
#pragma unroll
    for (int mt = 0; mt < 2; mt++)
#pragma unroll
        for (int nt = 0; nt < 8; nt++)
#pragma unroll
            for (int q = 0; q < 4; q++) acc[mt][nt][q] = 0.0f;

    int rowA = tid >> 1;            // 0..127
    int qA = (tid & 1) * 2;         // quad pair within 16-u32 slice

    const uint32_t* ArowH = Ah + (size_t)(m0 + rowA) * K2;
    const uint32_t* ArowL = Al + (size_t)(m0 + rowA) * K2;
    const uint32_t* BrowH = Bh + (size_t)(n0 + rowA) * K2;
    const uint32_t* BrowL = Bl + (size_t)(n0 + rowA) * K2;

    // prefetch slice 0 (all 4 planes)
    uint4 pah0 = *(const uint4*)(ArowH + qA * 4);
    uint4 pah1 = *(const uint4*)(ArowH + (qA + 1) * 4);
    uint4 pal0 = *(const uint4*)(ArowL + qA * 4);
    uint4 pal1 = *(const uint4*)(ArowL + (qA + 1) * 4);
    uint4 pbh0 = *(const uint4*)(BrowH + qA * 4);
    uint4 pbh1 = *(const uint4*)(BrowH + (qA + 1) * 4);
    uint4 pbl0 = *(const uint4*)(BrowL + qA * 4);
    uint4 pbl1 = *(const uint4*)(BrowL + (qA + 1) * 4);

    for (int kk = 0; kk < KC; kk++) {
        int sa = rowA * 20 + qA * 4;
        sAh[sa + 0] = pah0.x; sAh[sa + 1] = pah0.y; sAh[sa + 2] = pah0.z; sAh[sa + 3] = pah0.w;
        sAh[sa + 4] = pah1.x; sAh[sa + 5] = pah1.y; sAh[sa + 6] = pah1.z; sAh[sa + 7] = pah1.w;
        sAl[sa + 0] = pal0.x; sAl[sa + 1] = pal0.y; sAl[sa + 2] = pal0.z; sAl[sa + 3] = pal0.w;
        sAl[sa + 4] = pal1.x; sAl[sa + 5] = pal1.y; sAl[sa + 6] = pal1.z; sAl[sa + 7] = pal1.w;
        sBh[sa + 0] = pbh0.x; sBh[sa + 1] = pbh0.y; sBh[sa + 2] = pbh0.z; sBh[sa + 3] = pbh0.w;
        sBh[sa + 4] = pbh1.x; sBh[sa + 5] = pbh1.y; sBh[sa + 6] = pbh1.z; sBh[sa + 7] = pbh1.w;
        sBl[sa + 0] = pbl0.x; sBl[sa + 1] = pbl0.y; sBl[sa + 2] = pbl0.z; sBl[sa + 3] = pbl0.w;
        sBl[sa + 4] = pbl1.x; sBl[sa + 5] = pbl1.y; sBl[sa + 6] = pbl1.z; sBl[sa + 7] = pbl1.w;
        __syncthreads();

        if (kk + 1 < KC) {   // prefetch next slice into regs (lands during compute)
            int kku = (kk + 1) * 16;
            pah0 = *(const uint4*)(ArowH + kku + qA * 4);
            pah1 = *(const uint4*)(ArowH + kku + (qA + 1) * 4);
            pal0 = *(const uint4*)(ArowL + kku + qA * 4);
            pal1 = *(const uint4*)(ArowL + kku + (qA + 1) * 4);
            pbh0 = *(const uint4*)(BrowH + kku + qA * 4);
            pbh1 = *(const uint4*)(BrowH + kku + (qA + 1) * 4);
            pbl0 = *(const uint4*)(BrowL + kku + qA * 4);
            pbl1 = *(const uint4*)(BrowL + kku + (qA + 1) * 4);
        }

        // 3 terms from smem: Ah*Bh, Ah*Bl, Al*Bh
#pragma unroll
        for (int t = 0; t < 3; t++) {
            const uint32_t* As_ = (t == 2) ? sAl : sAh;
            const uint32_t* Bs_ = (t == 1) ? sBl : sBh;
#pragma unroll
            for (int kk8 = 0; kk8 < 16; kk8 += 8) {
                int ra = (wm + g) * 20 + kk8 + tg;
                uint32_t a00 = As_[ra];
                uint32_t a01 = As_[ra + 8 * 20];
                uint32_t a02 = As_[ra + 4];
                uint32_t a03 = As_[ra + 8 * 20 + 4];
                uint32_t a10 = As_[ra + 16 * 20];
                uint32_t a11 = As_[ra + 24 * 20];
                uint32_t a12 = As_[ra + 16 * 20 + 4];
                uint32_t a13 = As_[ra + 24 * 20 + 4];
#pragma unroll
                for (int nt = 0; nt < 8; nt++) {
                    int rb = (wn + nt * 8 + g) * 20 + kk8 + tg;
                    uint32_t b0 = Bs_[rb];
                    uint32_t b1 = Bs_[rb + 4];
                    MMA(acc[0][nt][0], acc[0][nt][1], acc[0][nt][2], acc[0][nt][3],
                        a00, a01, a02, a03, b0, b1);
                    MMA(acc[1][nt][0], acc[1][nt][1], acc[1][nt][2], acc[1][nt][3],
                        a10, a11, a12, a13, b0, b1);
                }
            }
        }
        __syncthreads();
    }

    // epilogue
    int K2out = Ntot >> 1;
#pragma unroll
    for (int mt = 0; mt < 2; mt++)
#pragma unroll
        for (int nt = 0; nt < 8; nt++) {
            int col = n0 + wn + nt * 8 + tg * 2;
            float v0 = acc[mt][nt][0], v1 = acc[mt][nt][1];
            float v2 = acc[mt][nt][2], v3 = acc[mt][nt][3];
            if (HASB) {
                float b0v = bias[col], b1v = bias[col + 1];
                v0 += b0v; v1 += b1v; v2 += b0v; v3 += b1v;
            }
            if (RELU) {
                v0 = fmaxf(v0, 0.0f); v1 = fmaxf(v1, 0.0f);
                v2 = fmaxf(v2, 0.0f); v3 = fmaxf(v3, 0.0f);
            }
            int r = m0 + wm + mt * 16 + g;
            if (!OUTS) {
                if (r < NN) {
                    C[(size_t)r * Ntot + col] = v0;
                    C[(size_t)r * Ntot + col + 1] = v1;
                }
                if (r + 8 < NN) {
                    C[(size_t)(r + 8) * Ntot + col] = v2;
                    C[(size_t)(r + 8) * Ntot + col + 1] = v3;
                }
            } else {
                if (r < NN) {
                    uint32_t h0 = f2bf(v0), h1 = f2bf(v1);
                    uint32_t l0 = f2bf(v0 - __uint_as_float(h0 << 16));
                    uint32_t l1 = f2bf(v1 - __uint_as_float(h1 << 16));
                    size_t idx = (size_t)r * K2out + (col >> 1);
                    OH[idx] = h0 | (h1 << 16);
                    OL[idx] = l0 | (l1 << 16);
                }
                if (r + 8 < NN) {
                    uint32_t h2 = f2bf(v2), h3 = f2bf(v3);
                    uint32_t l2 = f2bf(v2 - __uint_as_float(h2 << 16));
                    uint32_t l3 = f2bf(v3 - __uint_as_float(h3 << 16));
                    size_t idx = (size_t)(r + 8) * K2out + (col >> 1);
                    OH[idx] = h2 | (h3 << 16);
                    OL[idx] = l2 | (l3 << 16);
                }
            }
        }
}

__global__ void __launch_bounds__(256) kg1(const float* __restrict__ b1) {
    mm_body<true, true, true>(gA256h, gA256l, gB1h, gB1l, b1,
                              nullptr, gA512h, gA512l, 512, 256);
}
__global__ void __launch_bounds__(256) kg2() {
    mm_body<false, false, false>(gA512h, gA512l, gB2h, gB2l, nullptr,
                                 g_t2, nullptr, nullptr, 256, 512);
}
__global__ void __launch_bounds__(256) kg3() {
    mm_body<false, false, false>(gA256h, gA256l, gB3h, gB3l, nullptr,
                                 g_t3, nullptr, nullptr, 128, 256);
}

// ---------------- launch (ONLY harness pointers cross the host/device boundary) ----------------
extern "C" void kernel_launch(void* const* d_in, const int* in_sizes, int n_in,
                              void* d_out, int out_size) {
    const float* x  = (const float*)d_in[0];
    const int*   ei = (const int*)d_in[1];   // int32 edge_index, shape (2, NE)
    const float* w  = (const float*)d_in[2];
    const float* W1 = (const float*)d_in[3];
    const float* b1 = (const float*)d_in[4];
    const float* W2 = (const float*)d_in[5];
    const float* b2 = (const float*)d_in[6];
    const float* W3 = (const float*)d_in[7];
    const float* b3 = (const float*)d_in[8];
    float* out = (float*)d_out;

    // --- setup (init + weight splits), then CSR build ---
    k_setup<<<772, 256>>>(W1, W2, W3);
    k_deg<<<(NE + 255) / 256, 256>>>(ei, w);
    k_scan1<<<NBLK, 256>>>();     // + fused dinv
    k_scan3<<<NBLK, 256>>>();     // base derived in-kernel (scan2 folded in)
    k_scatter<<<(NE + 255) / 256, 256>>>(ei, w);

    const int aggBlocks = (NN * 32 + 255) / 256;
    const int mTiles = NN_PAD / 128;  // 391

    // layer 1: agg(x) -> planes; GEMM(256->512)+bias+relu -> planes (h1)
    k_agg1<<<aggBlocks, 256>>>(x);
    { dim3 gd(mTiles, 4); kg1<<<gd, 256>>>(b1); }

    // layer 2: GEMM(512->256) -> t2 (fp32); agg+bias+relu -> planes (h2)
    { dim3 gd(mTiles, 2); kg2<<<gd, 256>>>(); }
    k_agg2<<<aggBlocks, 256>>>(b2);

    // layer 3: GEMM(256->128) -> t3 (fp32); agg+bias -> out
    { dim3 gd(mTiles, 1); kg3<<<gd, 256>>>(); }
    k_agg3<<<aggBlocks, 256>>>(b3, out);
}